// round 1
// baseline (speedup 1.0000x reference)
#include <cuda_runtime.h>
#include <math.h>

// SparQ attention, B=8 H=32 S=4096 D=128 q_len=1 r=16 k=256, mask all-true.
static constexpr int BH   = 256;   // B*H
static constexpr int Sc   = 4096;
static constexpr int Dc   = 128;
static constexpr int Rc   = 16;
static constexpr int Ks   = 256;   // k (top-k rows)
static constexpr int NCH  = 8;     // S chunks for the big sweep kernel
static constexpr int CHS  = Sc / NCH;   // 512

// ---------------- scratch (device globals; no allocation allowed) ----------
__device__ float        g_logits[BH * Sc];
__device__ int          g_i1[BH * Rc];
__device__ float        g_qhat[BH * Rc];
__device__ float        g_scale[BH];
__device__ unsigned int g_gmax[BH];
__device__ float        g_vsum[BH * NCH * Dc];
__device__ int          g_sel[BH * Ks];
__device__ float        g_alpha[BH];

// ordered-uint mapping: monotone float <-> uint
__device__ __forceinline__ unsigned int f2o(float f) {
    unsigned int u = __float_as_uint(f);
    return u ^ ((u >> 31) ? 0xFFFFFFFFu : 0x80000000u);
}
__device__ __forceinline__ float o2f(unsigned int k) {
    unsigned int u = k ^ ((k >> 31) ? 0x80000000u : 0xFFFFFFFFu);
    return __uint_as_float(u);
}

// ---------------- kernel A: per-(b,h) top-16 |Q| dims + scale --------------
__global__ void kA(const float* __restrict__ Q) {
    int bh = blockIdx.x;
    int d  = threadIdx.x;          // 128 threads
    __shared__ float sa[Dc];
    __shared__ float stop[Rc];
    float q = Q[bh * Dc + d];
    float a = fabsf(q);
    sa[d] = a;
    __syncthreads();
    int rank = 0;
    float sumAll = 0.f;
    #pragma unroll 8
    for (int j = 0; j < Dc; j++) {
        float aj = sa[j];
        sumAll += aj;
        rank += (aj > a) || (aj == a && j < d);   // stable tie-break, unique ranks
    }
    if (rank < Rc) {
        g_i1[bh * Rc + rank]   = d;
        g_qhat[bh * Rc + rank] = q;
        stop[rank] = a;
    }
    __syncthreads();
    if (d == 0) {
        float st = 0.f;
        #pragma unroll
        for (int j = 0; j < Rc; j++) st += stop[j];
        g_scale[bh] = sqrtf((float)Dc * st / sumAll);
        g_gmax[bh]  = 0u;                         // below any finite ordered key
    }
}

// ---------------- kernel B: approximate logits + V column-sum sweep --------
// grid = BH*NCH blocks, 256 threads. The big HBM sweep: reads ~10/16 sectors of
// each K row (16-dim gather) + all of V.
__global__ void kB(const float* __restrict__ K, const float* __restrict__ V) {
    int bh  = blockIdx.x >> 3;
    int ch  = blockIdx.x & 7;
    int tid = threadIdx.x;

    __shared__ int   si1[Rc];
    __shared__ float sq[Rc];
    __shared__ float sscale;
    if (tid < Rc) { si1[tid] = g_i1[bh * Rc + tid]; sq[tid] = g_qhat[bh * Rc + tid]; }
    if (tid == 0) sscale = g_scale[bh];
    __syncthreads();

    const float inv_scale = 1.0f / sscale;
    const size_t base = (size_t)bh * Sc * Dc;
    const int s0 = ch * CHS;

    // --- approximate logits for 512 rows (2 per thread) ---
    float lmax = -INFINITY;
    #pragma unroll
    for (int it = 0; it < 2; it++) {
        int s = s0 + it * 256 + tid;
        const float* kr = K + base + (size_t)s * Dc;
        float acc = 0.f;
        #pragma unroll
        for (int j = 0; j < Rc; j++) acc += sq[j] * __ldg(kr + si1[j]);
        float lg = acc * inv_scale;
        g_logits[bh * Sc + s] = lg;
        lmax = fmaxf(lmax, lg);
    }
    #pragma unroll
    for (int o = 16; o; o >>= 1) lmax = fmaxf(lmax, __shfl_xor_sync(~0u, lmax, o));
    __shared__ float wmax[8];
    if ((tid & 31) == 0) wmax[tid >> 5] = lmax;
    __syncthreads();
    if (tid == 0) {
        float m = wmax[0];
        #pragma unroll
        for (int w = 1; w < 8; w++) m = fmaxf(m, wmax[w]);
        atomicMax(&g_gmax[bh], f2o(m));
    }

    // --- V partial column sums (coalesced float4 sweep) ---
    int lane4 = tid & 31;   // 32 float4 columns cover D=128
    int rgrp  = tid >> 5;   // 8 rows in flight
    const float4* V4 = (const float4*)(V + base);
    float4 acc4 = make_float4(0.f, 0.f, 0.f, 0.f);
    for (int s = s0 + rgrp; s < s0 + CHS; s += 8) {
        float4 v = __ldg(&V4[(size_t)s * 32 + lane4]);
        acc4.x += v.x; acc4.y += v.y; acc4.z += v.z; acc4.w += v.w;
    }
    __shared__ float4 sv[8][32];
    sv[rgrp][lane4] = acc4;
    __syncthreads();
    if (rgrp == 0) {
        float4 t = sv[0][lane4];
        #pragma unroll
        for (int g = 1; g < 8; g++) {
            float4 u = sv[g][lane4];
            t.x += u.x; t.y += u.y; t.z += u.z; t.w += u.w;
        }
        float4* o = (float4*)&g_vsum[(bh * NCH + ch) * Dc];
        o[lane4] = t;
    }
}

// ---------------- kernel C: exact top-256 select + sumexp + alpha ----------
// 256 blocks x 256 threads. In-SMEM radix select over ordered-uint keys:
// identical selection set to jax.lax.top_k (ties -> smallest index).
__global__ void kC() {
    int bh  = blockIdx.x;
    int tid = threadIdx.x;

    __shared__ unsigned int keys[Sc];      // 16 KB
    __shared__ unsigned int hist[256];
    __shared__ int sel[Ks];
    __shared__ float sred[8];
    __shared__ unsigned int s_prefix;
    __shared__ int s_remaining;
    __shared__ int cnt;
    __shared__ int tie_taken;
    __shared__ int wtot[8];
    __shared__ float s_sumexp;

    const float gmax = o2f(g_gmax[bh]);

    float lsum = 0.f;
    for (int s = tid; s < Sc; s += 256) {
        float lg = g_logits[bh * Sc + s];
        keys[s] = f2o(lg);
        lsum += __expf(lg - gmax);
    }
    // block-reduce sumexp
    #pragma unroll
    for (int o = 16; o; o >>= 1) lsum += __shfl_xor_sync(~0u, lsum, o);
    if ((tid & 31) == 0) sred[tid >> 5] = lsum;
    __syncthreads();
    if (tid == 0) {
        float t = 0.f;
        #pragma unroll
        for (int w = 0; w < 8; w++) t += sred[w];
        s_sumexp = t;
        s_prefix = 0u;
        s_remaining = Ks;
        cnt = 0;
        tie_taken = 0;
    }
    __syncthreads();

    // 4-pass radix select (MSB first) for the 256th-largest key
    for (int shift = 24; shift >= 0; shift -= 8) {
        hist[tid] = 0u;
        __syncthreads();
        unsigned int pre   = s_prefix;
        unsigned int pmask = (shift == 24) ? 0u : (0xFFFFFFFFu << (shift + 8));
        for (int s = tid; s < Sc; s += 256) {
            unsigned int kk = keys[s];
            if ((kk & pmask) == pre) atomicAdd(&hist[(kk >> shift) & 0xFFu], 1u);
        }
        __syncthreads();
        if (tid == 0) {
            int rem = s_remaining;
            int dsel = 0;
            for (int dgt = 255; dgt >= 0; dgt--) {
                int c = (int)hist[dgt];
                if (rem <= c) { dsel = dgt; break; }
                rem -= c;
            }
            s_remaining = rem;
            s_prefix = pre | ((unsigned int)dsel << shift);
        }
        __syncthreads();
    }
    const unsigned int T = s_prefix;    // exact 256th-largest key
    const int need_ties  = s_remaining; // how many == T to take
    const int n_greater  = Ks - need_ties;

    // all strictly-greater keys (order irrelevant)
    for (int s = tid; s < Sc; s += 256) {
        if (keys[s] > T) { int p = atomicAdd(&cnt, 1); sel[p] = s; }
    }
    __syncthreads();
    // ties: deterministic ascending-index compaction
    int lane = tid & 31, wid = tid >> 5;
    for (int basei = 0; basei < Sc; basei += 256) {
        __syncthreads();
        int s = basei + tid;
        bool pred = (keys[s] == T);
        unsigned int bal = __ballot_sync(~0u, pred);
        if (lane == 0) wtot[wid] = __popc(bal);
        __syncthreads();
        int t0 = tie_taken;
        int off = 0, tot = 0;
        #pragma unroll
        for (int w = 0; w < 8; w++) { int c = wtot[w]; if (w < wid) off += c; tot += c; }
        if (pred) {
            int rnk = t0 + off + __popc(bal & ((1u << lane) - 1u));
            if (rnk < need_ties) sel[n_greater + rnk] = s;
        }
        __syncthreads();
        if (tid == 0) tie_taken = t0 + tot;
    }
    __syncthreads();

    // alpha = sum_{sel} exp(l - gmax) / sumexp ; store sel
    int mysel = sel[tid];                       // blockDim == Ks == 256
    float e = __expf(o2f(keys[mysel]) - gmax);
    #pragma unroll
    for (int o = 16; o; o >>= 1) e += __shfl_xor_sync(~0u, e, o);
    if ((tid & 31) == 0) sred[tid >> 5] = e;
    __syncthreads();
    if (tid == 0) {
        float num = 0.f;
        #pragma unroll
        for (int w = 0; w < 8; w++) num += sred[w];
        g_alpha[bh] = num / s_sumexp;
    }
    g_sel[bh * Ks + tid] = mysel;
}

// ---------------- kernel E: exact attention on 256 rows + combine ----------
__global__ void kE(const float* __restrict__ Q, const float* __restrict__ K,
                   const float* __restrict__ V, float* __restrict__ out) {
    int bh  = blockIdx.x;
    int tid = threadIdx.x;        // 128 threads
    int lane = tid & 31, wid = tid >> 5;

    __shared__ float sq[Dc];
    __shared__ int   sel[Ks];
    __shared__ float w[Ks];
    __shared__ float sred[4];

    sq[tid] = Q[bh * Dc + tid];
    sel[tid]       = g_sel[bh * Ks + tid];
    sel[tid + 128] = g_sel[bh * Ks + tid + 128];
    __syncthreads();

    const size_t base = (size_t)bh * Sc * Dc;
    const float inv_sqrtD = 0.08838834764831845f;  // 1/sqrt(128)

    // QK over selected rows: each warp handles rows wid, wid+4, ...
    for (int r = wid; r < Ks; r += 4) {
        const float* kr = K + base + (size_t)sel[r] * Dc;
        float acc = 0.f;
        #pragma unroll
        for (int j = lane; j < Dc; j += 32) acc += sq[j] * __ldg(kr + j);
        #pragma unroll
        for (int o = 16; o; o >>= 1) acc += __shfl_xor_sync(~0u, acc, o);
        if (lane == 0) w[r] = acc * inv_sqrtD;
    }
    __syncthreads();

    // softmax over 256
    float m = fmaxf(w[tid], w[tid + 128]);
    #pragma unroll
    for (int o = 16; o; o >>= 1) m = fmaxf(m, __shfl_xor_sync(~0u, m, o));
    if (lane == 0) sred[wid] = m;
    __syncthreads();
    m = fmaxf(fmaxf(sred[0], sred[1]), fmaxf(sred[2], sred[3]));

    float e0 = __expf(w[tid]       - m);
    float e1 = __expf(w[tid + 128] - m);
    w[tid]       = e0;
    w[tid + 128] = e1;
    float ls = e0 + e1;
    #pragma unroll
    for (int o = 16; o; o >>= 1) ls += __shfl_xor_sync(~0u, ls, o);
    if (lane == 0) sred[wid] = ls;
    __syncthreads();
    float ssum = sred[0] + sred[1] + sred[2] + sred[3];

    // y[d] = (sum_r w[r] * V[sel[r], d]) / ssum
    float y = 0.f;
    #pragma unroll 4
    for (int r = 0; r < Ks; r++) {
        y += w[r] * __ldg(V + base + (size_t)sel[r] * Dc + tid);
    }
    y /= ssum;

    // V_mean (mask all-true -> divide by S)
    float vm = 0.f;
    #pragma unroll
    for (int c = 0; c < NCH; c++) vm += g_vsum[(bh * NCH + c) * Dc + tid];
    vm *= (1.0f / (float)Sc);

    float alpha = g_alpha[bh];
    out[bh * Dc + tid] = vm + alpha * (y - vm);
}

// ---------------- launch ----------------------------------------------------
extern "C" void kernel_launch(void* const* d_in, const int* in_sizes, int n_in,
                              void* d_out, int out_size) {
    const float* Q = (const float*)d_in[0];
    const float* K = (const float*)d_in[1];
    const float* V = (const float*)d_in[2];
    // d_in[3] = mask (all true by construction), d_in[4]=r, d_in[5]=k : compile-time here
    float* out = (float*)d_out;

    kA<<<BH, Dc>>>(Q);
    kB<<<BH * NCH, 256>>>(K, V);
    kC<<<BH, 256>>>();
    kE<<<BH, Dc>>>(Q, K, V, out);
}

// round 2
// speedup vs baseline: 1.3417x; 1.3417x over previous
#include <cuda_runtime.h>
#include <math.h>

// SparQ attention, B=8 H=32 S=4096 D=128 q_len=1 r=16 k=256, mask all-true.
static constexpr int BH  = 256;
static constexpr int Sc  = 4096;
static constexpr int Dc  = 128;
static constexpr int Rc  = 16;
static constexpr int Ks  = 256;
static constexpr int NCH = 8;
static constexpr int CHS = Sc / NCH;   // 512

__device__ float g_logits[BH * Sc];
__device__ float g_vsum[BH * NCH * Dc];

__device__ __forceinline__ unsigned int f2o(float f) {
    unsigned int u = __float_as_uint(f);
    return u ^ ((u >> 31) ? 0xFFFFFFFFu : 0x80000000u);
}
__device__ __forceinline__ float o2f(unsigned int k) {
    unsigned int u = k ^ ((k >> 31) ? 0x80000000u : 0xFFFFFFFFu);
    return __uint_as_float(u);
}

// ---------------- kernel B: inline top-16(|Q|) + approx logits + V sweep ----
// grid = BH*NCH (2048) blocks, 256 threads.
__global__ void kB(const float* __restrict__ Q, const float* __restrict__ K,
                   const float* __restrict__ V) {
    int bh  = blockIdx.x >> 3;
    int ch  = blockIdx.x & 7;
    int tid = threadIdx.x;

    __shared__ float sa[Dc], sqf[Dc];
    __shared__ int   si1[Rc];
    __shared__ float sq[Rc], stop[Rc];
    __shared__ float s_sumAll, s_inv_scale;

    if (tid < Dc) {
        float q = Q[bh * Dc + tid];
        sqf[tid] = q;
        sa[tid]  = fabsf(q);
    }
    __syncthreads();
    if (tid < Dc) {
        float a = sa[tid];
        int rank = 0;
        float sumAll = 0.f;
        #pragma unroll 8
        for (int j = 0; j < Dc; j++) {
            float aj = sa[j];
            sumAll += aj;
            rank += (aj > a) || (aj == a && j < tid);   // unique ranks, jax tie order
        }
        if (rank < Rc) { si1[rank] = tid; sq[rank] = sqf[tid]; stop[rank] = a; }
        if (tid == 0) s_sumAll = sumAll;
    }
    __syncthreads();
    if (tid == 0) {
        float st = 0.f;
        #pragma unroll
        for (int j = 0; j < Rc; j++) st += stop[j];
        s_inv_scale = 1.0f / sqrtf((float)Dc * st / s_sumAll);
    }
    __syncthreads();

    const float inv_scale = s_inv_scale;
    const size_t base = (size_t)bh * Sc * Dc;
    const int s0 = ch * CHS;

    // approximate logits, 2 rows per thread (16 scattered 4B loads per row)
    #pragma unroll
    for (int it = 0; it < 2; it++) {
        int s = s0 + it * 256 + tid;
        const float* kr = K + base + (size_t)s * Dc;
        float acc = 0.f;
        #pragma unroll
        for (int j = 0; j < Rc; j++) acc += sq[j] * __ldg(kr + si1[j]);
        g_logits[bh * Sc + s] = acc * inv_scale;
    }

    // V partial column sums (coalesced float4 sweep)
    int lane4 = tid & 31;
    int rgrp  = tid >> 5;
    const float4* V4 = (const float4*)(V + base);
    float4 acc4 = make_float4(0.f, 0.f, 0.f, 0.f);
    #pragma unroll 8
    for (int s = s0 + rgrp; s < s0 + CHS; s += 8) {
        float4 v = __ldg(&V4[(size_t)s * 32 + lane4]);
        acc4.x += v.x; acc4.y += v.y; acc4.z += v.z; acc4.w += v.w;
    }
    __shared__ float4 sv[8][32];
    sv[rgrp][lane4] = acc4;
    __syncthreads();
    if (rgrp == 0) {
        float4 t = sv[0][lane4];
        #pragma unroll
        for (int g = 1; g < 8; g++) {
            float4 u = sv[g][lane4];
            t.x += u.x; t.y += u.y; t.z += u.z; t.w += u.w;
        }
        ((float4*)&g_vsum[(bh * NCH + ch) * Dc])[lane4] = t;
    }
}

// ---------------- kernel CE: top-256 select + alpha + exact attn + combine --
// grid = BH (256) blocks, 512 threads.
__global__ void __launch_bounds__(512) kCE(const float* __restrict__ Q,
                                           const float* __restrict__ K,
                                           const float* __restrict__ V,
                                           float* __restrict__ out) {
    int bh   = blockIdx.x;
    int tid  = threadIdx.x;
    int lane = tid & 31, wid = tid >> 5;

    __shared__ unsigned int keys[Sc];       // 16 KB
    __shared__ unsigned int hist[256];
    __shared__ int   sel[Ks];
    __shared__ float w[Ks];
    __shared__ float sq[Dc];
    __shared__ float sy[4][Dc];
    __shared__ float sred[16];
    __shared__ float s_gmax, s_sumexp, s_alpha, s_m, s_ssum;
    __shared__ unsigned int s_prefix;
    __shared__ int s_remaining, cnt, tie_taken, wtot[16];

    if (tid < Dc) sq[tid] = Q[bh * Dc + tid];

    // ---- load logits -> ordered keys, block max ----
    float lmax = -INFINITY;
    for (int s = tid; s < Sc; s += 512) {
        float lg = g_logits[bh * Sc + s];
        keys[s] = f2o(lg);
        lmax = fmaxf(lmax, lg);
    }
    #pragma unroll
    for (int o = 16; o; o >>= 1) lmax = fmaxf(lmax, __shfl_xor_sync(~0u, lmax, o));
    if (lane == 0) sred[wid] = lmax;
    __syncthreads();
    if (tid == 0) {
        float m = sred[0];
        #pragma unroll
        for (int i = 1; i < 16; i++) m = fmaxf(m, sred[i]);
        s_gmax = m;
        s_prefix = 0u; s_remaining = Ks; cnt = 0; tie_taken = 0;
    }
    __syncthreads();
    const float gmax = s_gmax;

    // ---- full sumexp ----
    float lsum = 0.f;
    for (int s = tid; s < Sc; s += 512) lsum += __expf(o2f(keys[s]) - gmax);
    #pragma unroll
    for (int o = 16; o; o >>= 1) lsum += __shfl_xor_sync(~0u, lsum, o);
    if (lane == 0) sred[wid] = lsum;
    __syncthreads();
    if (tid == 0) {
        float t = 0.f;
        #pragma unroll
        for (int i = 0; i < 16; i++) t += sred[i];
        s_sumexp = t;
    }
    __syncthreads();

    // ---- 4-pass radix select for the 256th-largest key ----
    for (int shift = 24; shift >= 0; shift -= 8) {
        if (tid < 256) hist[tid] = 0u;
        __syncthreads();
        unsigned int pre   = s_prefix;
        unsigned int pmask = (shift == 24) ? 0u : (0xFFFFFFFFu << (shift + 8));
        for (int s = tid; s < Sc; s += 512) {
            unsigned int kk = keys[s];
            if ((kk & pmask) == pre) atomicAdd(&hist[(kk >> shift) & 0xFFu], 1u);
        }
        __syncthreads();
        if (tid == 0) {
            int rem = s_remaining, dsel = 0;
            for (int dgt = 255; dgt >= 0; dgt--) {
                int c = (int)hist[dgt];
                if (rem <= c) { dsel = dgt; break; }
                rem -= c;
            }
            s_remaining = rem;
            s_prefix = pre | ((unsigned int)dsel << shift);
        }
        __syncthreads();
    }
    const unsigned int T = s_prefix;
    const int need_ties  = s_remaining;
    const int n_greater  = Ks - need_ties;

    // strictly greater (unordered)
    for (int s = tid; s < Sc; s += 512) {
        if (keys[s] > T) { int p = atomicAdd(&cnt, 1); sel[p] = s; }
    }
    __syncthreads();
    // ties: deterministic ascending-index compaction
    for (int basei = 0; basei < Sc; basei += 512) {
        int s = basei + tid;
        bool pred = (keys[s] == T);
        unsigned int bal = __ballot_sync(~0u, pred);
        if (lane == 0) wtot[wid] = __popc(bal);
        __syncthreads();
        int t0 = tie_taken;
        int off = 0, tot = 0;
        #pragma unroll
        for (int wI = 0; wI < 16; wI++) { int c = wtot[wI]; if (wI < wid) off += c; tot += c; }
        if (pred) {
            int rnk = t0 + off + __popc(bal & ((1u << lane) - 1u));
            if (rnk < need_ties) sel[n_greater + rnk] = s;
        }
        __syncthreads();
        if (tid == 0) tie_taken = t0 + tot;
        __syncthreads();
    }

    // ---- alpha = sum_sel exp(l-gmax) / sumexp ----
    float e = (tid < Ks) ? __expf(o2f(keys[sel[tid]]) - gmax) : 0.f;
    #pragma unroll
    for (int o = 16; o; o >>= 1) e += __shfl_xor_sync(~0u, e, o);
    if (lane == 0) sred[wid] = e;
    __syncthreads();
    if (tid == 0) {
        float num = 0.f;
        #pragma unroll
        for (int i = 0; i < 16; i++) num += sred[i];
        s_alpha = num / s_sumexp;
    }
    __syncthreads();

    // ---- exact QK over selected rows: one warp per row, float4 lanes ----
    const size_t base = (size_t)bh * Sc * Dc;
    const float inv_sqrtD = 0.08838834764831845f;
    float4 q4 = ((const float4*)sq)[lane];
    for (int r = wid; r < Ks; r += 16) {
        const float4* kr4 = (const float4*)(K + base + (size_t)sel[r] * Dc);
        float4 kv = __ldg(&kr4[lane]);
        float acc = q4.x * kv.x + q4.y * kv.y + q4.z * kv.z + q4.w * kv.w;
        #pragma unroll
        for (int o = 16; o; o >>= 1) acc += __shfl_xor_sync(~0u, acc, o);
        if (lane == 0) w[r] = acc * inv_sqrtD;
    }
    __syncthreads();

    // ---- softmax over 256 (threads 0..255) ----
    float m = (tid < Ks) ? w[tid] : -INFINITY;
    #pragma unroll
    for (int o = 16; o; o >>= 1) m = fmaxf(m, __shfl_xor_sync(~0u, m, o));
    if (lane == 0) sred[wid] = m;
    __syncthreads();
    if (tid == 0) {
        float mm = sred[0];
        #pragma unroll
        for (int i = 1; i < 8; i++) mm = fmaxf(mm, sred[i]);
        s_m = mm;
    }
    __syncthreads();
    float ev = (tid < Ks) ? __expf(w[tid] - s_m) : 0.f;
    __syncthreads();
    if (tid < Ks) w[tid] = ev;
    float ls = ev;
    #pragma unroll
    for (int o = 16; o; o >>= 1) ls += __shfl_xor_sync(~0u, ls, o);
    if (lane == 0) sred[wid] = ls;
    __syncthreads();
    if (tid == 0) {
        float t = 0.f;
        #pragma unroll
        for (int i = 0; i < 8; i++) t += sred[i];
        s_ssum = t;
    }
    __syncthreads();

    // ---- y = sum_r w[r] * V[sel[r], :] with 4 row-groups x 128 dims ----
    int rg = tid >> 7;      // 0..3
    int d  = tid & 127;
    float y = 0.f;
    #pragma unroll 8
    for (int r = rg; r < Ks; r += 4) {
        y += w[r] * __ldg(V + base + (size_t)sel[r] * Dc + d);
    }
    sy[rg][d] = y;
    __syncthreads();

    if (tid < Dc) {
        float yy = (sy[0][tid] + sy[1][tid] + sy[2][tid] + sy[3][tid]) / s_ssum;
        float vm = 0.f;
        #pragma unroll
        for (int c = 0; c < NCH; c++) vm += g_vsum[(bh * NCH + c) * Dc + tid];
        vm *= (1.0f / (float)Sc);
        out[bh * Dc + tid] = vm + s_alpha * (yy - vm);
    }
}

// ---------------- launch ----------------------------------------------------
extern "C" void kernel_launch(void* const* d_in, const int* in_sizes, int n_in,
                              void* d_out, int out_size) {
    const float* Q = (const float*)d_in[0];
    const float* K = (const float*)d_in[1];
    const float* V = (const float*)d_in[2];
    float* out = (float*)d_out;

    kB<<<BH * NCH, 256>>>(Q, K, V);
    kCE<<<BH, 512>>>(Q, K, V, out);
}

// round 3
// speedup vs baseline: 1.7394x; 1.2964x over previous
#include <cuda_runtime.h>
#include <math.h>

// SparQ attention, B=8 H=32 S=4096 D=128 q_len=1 r=16 k=256, mask all-true.
static constexpr int BH  = 256;
static constexpr int Sc  = 4096;
static constexpr int Dc  = 128;
static constexpr int Rc  = 16;
static constexpr int Ks  = 256;
static constexpr int NCH = 8;
static constexpr int CHS = Sc / NCH;   // 512

__device__ float g_logits[BH * Sc];
__device__ float g_vsum[BH * NCH * Dc];

__device__ __forceinline__ unsigned int f2o(float f) {
    unsigned int u = __float_as_uint(f);
    return u ^ ((u >> 31) ? 0xFFFFFFFFu : 0x80000000u);
}
__device__ __forceinline__ float o2f(unsigned int k) {
    unsigned int u = k ^ ((k >> 31) ? 0x80000000u : 0xFFFFFFFFu);
    return __uint_as_float(u);
}

// ---------------- kernel B: inline top-16(|Q|) + approx logits + V sweep ----
// grid = BH*NCH (2048) blocks, 256 threads.
__global__ void __launch_bounds__(256) kB(const float* __restrict__ Q,
                                          const float* __restrict__ K,
                                          const float* __restrict__ V) {
    int bh  = blockIdx.x >> 3;
    int ch  = blockIdx.x & 7;
    int tid = threadIdx.x;

    __shared__ float sa[Dc], sqf[Dc];
    __shared__ int   si1[Rc];
    __shared__ float sq[Rc], stop[Rc];
    __shared__ float s_sumAll, s_inv_scale;

    if (tid < Dc) {
        float q = Q[bh * Dc + tid];
        sqf[tid] = q;
        sa[tid]  = fabsf(q);
    }
    __syncthreads();
    if (tid < Dc) {
        float a = sa[tid];
        int rank = 0;
        float sumAll = 0.f;
        #pragma unroll 8
        for (int j = 0; j < Dc; j++) {
            float aj = sa[j];
            sumAll += aj;
            rank += (aj > a) || (aj == a && j < tid);   // unique ranks, jax tie order
        }
        if (rank < Rc) { si1[rank] = tid; sq[rank] = sqf[tid]; stop[rank] = a; }
        if (tid == 0) s_sumAll = sumAll;
    }
    __syncthreads();
    if (tid == 0) {
        float st = 0.f;
        #pragma unroll
        for (int j = 0; j < Rc; j++) st += stop[j];
        s_inv_scale = 1.0f / sqrtf((float)Dc * st / s_sumAll);
    }
    __syncthreads();

    const float inv_scale = s_inv_scale;
    const size_t base = (size_t)bh * Sc * Dc;
    const int s0 = ch * CHS;

    // ---- approx logits: one HALF-WARP per row (lanes j=0..15 load si1[j]) ----
    // warp w, half h handles rows s0 + (it*8 + w)*2 + h, it = 0..31
    {
        int warp = tid >> 5, lane = tid & 31;
        int half = lane >> 4;
        int j    = lane & 15;
        const int   cidx = si1[j];
        const float qj   = sq[j];
        const float* Kc  = K + base + cidx;
        #pragma unroll
        for (int ot = 0; ot < 8; ot++) {
            float v[4]; int ss[4];
            #pragma unroll
            for (int u = 0; u < 4; u++) {
                int it = ot * 4 + u;
                ss[u] = s0 + (it * 8 + warp) * 2 + half;
                v[u]  = __ldg(Kc + (size_t)ss[u] * Dc);
            }
            #pragma unroll
            for (int u = 0; u < 4; u++) {
                float p = qj * v[u];
                #pragma unroll
                for (int o = 8; o; o >>= 1) p += __shfl_down_sync(~0u, p, o, 16);
                if (j == 0) g_logits[bh * Sc + ss[u]] = p * inv_scale;
            }
        }
    }

    // ---- V partial column sums (coalesced float4 sweep) ----
    int lane4 = tid & 31;
    int rgrp  = tid >> 5;
    const float4* V4 = (const float4*)(V + base);
    float4 acc4 = make_float4(0.f, 0.f, 0.f, 0.f);
    #pragma unroll 8
    for (int s = s0 + rgrp; s < s0 + CHS; s += 8) {
        float4 v = __ldg(&V4[(size_t)s * 32 + lane4]);
        acc4.x += v.x; acc4.y += v.y; acc4.z += v.z; acc4.w += v.w;
    }
    __shared__ float4 sv[8][32];
    sv[rgrp][lane4] = acc4;
    __syncthreads();
    if (rgrp == 0) {
        float4 t = sv[0][lane4];
        #pragma unroll
        for (int g = 1; g < 8; g++) {
            float4 u = sv[g][lane4];
            t.x += u.x; t.y += u.y; t.z += u.z; t.w += u.w;
        }
        ((float4*)&g_vsum[(bh * NCH + ch) * Dc])[lane4] = t;
    }
}

// ---------------- kernel CE: top-256 select + alpha + exact attn + combine --
// grid = BH (256) blocks, 1024 threads.
__global__ void __launch_bounds__(1024) kCE(const float* __restrict__ Q,
                                            const float* __restrict__ K,
                                            const float* __restrict__ V,
                                            float* __restrict__ out) {
    int bh   = blockIdx.x;
    int tid  = threadIdx.x;
    int lane = tid & 31, wid = tid >> 5;   // 32 warps

    __shared__ unsigned int keys[Sc];       // 16 KB
    __shared__ unsigned int hist[256];
    __shared__ int   sel[Ks];
    __shared__ float w[Ks];
    __shared__ float sq[Dc];
    __shared__ float sy[8][Dc];             // 4 KB
    __shared__ float sred[32];
    __shared__ float s_gmax, s_sumexp, s_alpha, s_m, s_ssum;
    __shared__ unsigned int s_prefix;
    __shared__ int s_remaining, cnt, tie_taken, wtot[32];

    if (tid < Dc) sq[tid] = Q[bh * Dc + tid];

    // ---- load logits -> ordered keys, block max + sumexp prep ----
    float lmax = -INFINITY;
    #pragma unroll
    for (int i = 0; i < 4; i++) {
        int s = tid + i * 1024;
        float lg = g_logits[bh * Sc + s];
        keys[s] = f2o(lg);
        lmax = fmaxf(lmax, lg);
    }
    #pragma unroll
    for (int o = 16; o; o >>= 1) lmax = fmaxf(lmax, __shfl_xor_sync(~0u, lmax, o));
    if (lane == 0) sred[wid] = lmax;
    __syncthreads();
    if (tid == 0) {
        float m = sred[0];
        #pragma unroll
        for (int i = 1; i < 32; i++) m = fmaxf(m, sred[i]);
        s_gmax = m;
        s_prefix = 0u; s_remaining = Ks; cnt = 0; tie_taken = 0;
    }
    __syncthreads();
    const float gmax = s_gmax;

    // ---- full sumexp ----
    float lsum = 0.f;
    #pragma unroll
    for (int i = 0; i < 4; i++) lsum += __expf(o2f(keys[tid + i * 1024]) - gmax);
    #pragma unroll
    for (int o = 16; o; o >>= 1) lsum += __shfl_xor_sync(~0u, lsum, o);
    if (lane == 0) sred[wid] = lsum;
    __syncthreads();
    if (tid == 0) {
        float t = 0.f;
        #pragma unroll
        for (int i = 0; i < 32; i++) t += sred[i];
        s_sumexp = t;
    }
    __syncthreads();

    // ---- 4-pass radix select for the 256th-largest key ----
    for (int shift = 24; shift >= 0; shift -= 8) {
        if (tid < 256) hist[tid] = 0u;
        __syncthreads();
        unsigned int pre   = s_prefix;
        unsigned int pmask = (shift == 24) ? 0u : (0xFFFFFFFFu << (shift + 8));
        #pragma unroll
        for (int i = 0; i < 4; i++) {
            unsigned int kk = keys[tid + i * 1024];
            if ((kk & pmask) == pre) atomicAdd(&hist[(kk >> shift) & 0xFFu], 1u);
        }
        __syncthreads();
        if (tid == 0) {
            int rem = s_remaining, dsel = 0;
            for (int dgt = 255; dgt >= 0; dgt--) {
                int c = (int)hist[dgt];
                if (rem <= c) { dsel = dgt; break; }
                rem -= c;
            }
            s_remaining = rem;
            s_prefix = pre | ((unsigned int)dsel << shift);
        }
        __syncthreads();
    }
    const unsigned int T = s_prefix;
    const int need_ties  = s_remaining;
    const int n_greater  = Ks - need_ties;

    // strictly greater (unordered)
    #pragma unroll
    for (int i = 0; i < 4; i++) {
        int s = tid + i * 1024;
        if (keys[s] > T) { int p = atomicAdd(&cnt, 1); sel[p] = s; }
    }
    __syncthreads();
    // ties: deterministic ascending-index compaction
    for (int basei = 0; basei < Sc; basei += 1024) {
        int s = basei + tid;
        bool pred = (keys[s] == T);
        unsigned int bal = __ballot_sync(~0u, pred);
        if (lane == 0) wtot[wid] = __popc(bal);
        __syncthreads();
        int t0 = tie_taken;
        int off = 0, tot = 0;
        #pragma unroll
        for (int wI = 0; wI < 32; wI++) { int c = wtot[wI]; if (wI < wid) off += c; tot += c; }
        if (pred) {
            int rnk = t0 + off + __popc(bal & ((1u << lane) - 1u));
            if (rnk < need_ties) sel[n_greater + rnk] = s;
        }
        __syncthreads();
        if (tid == 0) tie_taken = t0 + tot;
        __syncthreads();
    }

    // ---- alpha = sum_sel exp(l-gmax) / sumexp ----
    float e = (tid < Ks) ? __expf(o2f(keys[sel[tid]]) - gmax) : 0.f;
    #pragma unroll
    for (int o = 16; o; o >>= 1) e += __shfl_xor_sync(~0u, e, o);
    if (lane == 0) sred[wid] = e;
    __syncthreads();
    if (tid == 0) {
        float num = 0.f;
        #pragma unroll
        for (int i = 0; i < 8; i++) num += sred[i];   // only warps 0..7 have tid<256
        s_alpha = num / s_sumexp;
    }
    __syncthreads();

    // ---- exact QK over selected rows: one warp per row, float4 lanes ----
    const size_t base = (size_t)bh * Sc * Dc;
    const float inv_sqrtD = 0.08838834764831845f;
    float4 q4 = ((const float4*)sq)[lane];
    #pragma unroll
    for (int rr = 0; rr < 8; rr++) {
        int r = wid + rr * 32;
        const float4* kr4 = (const float4*)(K + base + (size_t)sel[r] * Dc);
        float4 kv = __ldg(&kr4[lane]);
        float acc = q4.x * kv.x + q4.y * kv.y + q4.z * kv.z + q4.w * kv.w;
        #pragma unroll
        for (int o = 16; o; o >>= 1) acc += __shfl_xor_sync(~0u, acc, o);
        if (lane == 0) w[r] = acc * inv_sqrtD;
    }
    __syncthreads();

    // ---- softmax over 256 (threads 0..255) ----
    float m = (tid < Ks) ? w[tid] : -INFINITY;
    #pragma unroll
    for (int o = 16; o; o >>= 1) m = fmaxf(m, __shfl_xor_sync(~0u, m, o));
    if (lane == 0) sred[wid] = m;
    __syncthreads();
    if (tid == 0) {
        float mm = sred[0];
        #pragma unroll
        for (int i = 1; i < 8; i++) mm = fmaxf(mm, sred[i]);
        s_m = mm;
    }
    __syncthreads();
    float ev = (tid < Ks) ? __expf(w[tid] - s_m) : 0.f;
    __syncthreads();
    if (tid < Ks) w[tid] = ev;
    float ls = ev;
    #pragma unroll
    for (int o = 16; o; o >>= 1) ls += __shfl_xor_sync(~0u, ls, o);
    if (lane == 0) sred[wid] = ls;
    __syncthreads();
    if (tid == 0) {
        float t = 0.f;
        #pragma unroll
        for (int i = 0; i < 8; i++) t += sred[i];
        s_ssum = t;
    }
    __syncthreads();

    // ---- y = sum_r w[r] * V[sel[r], :] with 8 row-groups x 128 dims ----
    int rg = tid >> 7;      // 0..7
    int d  = tid & 127;
    float y = 0.f;
    #pragma unroll 8
    for (int r = rg; r < Ks; r += 8) {
        y += w[r] * __ldg(V + base + (size_t)sel[r] * Dc + d);
    }
    sy[rg][d] = y;
    __syncthreads();

    if (tid < Dc) {
        float yy = 0.f;
        #pragma unroll
        for (int g = 0; g < 8; g++) yy += sy[g][tid];
        yy /= s_ssum;
        float vm = 0.f;
        #pragma unroll
        for (int c = 0; c < NCH; c++) vm += g_vsum[(bh * NCH + c) * Dc + tid];
        vm *= (1.0f / (float)Sc);
        out[bh * Dc + tid] = vm + s_alpha * (yy - vm);
    }
}

// ---------------- launch ----------------------------------------------------
extern "C" void kernel_launch(void* const* d_in, const int* in_sizes, int n_in,
                              void* d_out, int out_size) {
    const float* Q = (const float*)d_in[0];
    const float* K = (const float*)d_in[1];
    const float* V = (const float*)d_in[2];
    float* out = (float*)d_out;

    kB<<<BH * NCH, 256>>>(Q, K, V);
    kCE<<<BH, 1024>>>(Q, K, V, out);
}

// round 5
// speedup vs baseline: 1.7904x; 1.0293x over previous
#include <cuda_runtime.h>
#include <math.h>

// SparQ attention, B=8 H=32 S=4096 D=128 q_len=1 r=16 k=256, mask all-true.
static constexpr int BH  = 256;
static constexpr int Sc  = 4096;
static constexpr int Dc  = 128;
static constexpr int Rc  = 16;
static constexpr int Ks  = 256;
static constexpr int NCH = 8;
static constexpr int CHS = Sc / NCH;   // 512

__device__ unsigned int g_keys[BH * Sc];     // ordered-uint logits
__device__ float        g_vsum[BH * NCH * Dc];

__device__ __forceinline__ unsigned int f2o(float f) {
    unsigned int u = __float_as_uint(f);
    return u ^ ((u >> 31) ? 0xFFFFFFFFu : 0x80000000u);
}
__device__ __forceinline__ float o2f(unsigned int k) {
    unsigned int u = k ^ ((k >> 31) ? 0x80000000u : 0xFFFFFFFFu);
    return __uint_as_float(u);
}

// ---------------- kernel B: heterogeneous blocks -----------------------------
// grid = 2*BH*NCH (4096) blocks of 256 threads.
// even blocks: top-16(|Q|) + approximate logits for one 512-row chunk
// odd  blocks: V partial column sums for one 512-row chunk
__global__ void __launch_bounds__(256) kB(const float* __restrict__ Q,
                                          const float* __restrict__ K,
                                          const float* __restrict__ V) {
    int id  = blockIdx.x >> 1;
    int bh  = id >> 3;
    int ch  = id & 7;
    int tid = threadIdx.x;
    const size_t base = (size_t)bh * Sc * Dc;
    const int s0 = ch * CHS;

    if (blockIdx.x & 1) {
        // ---- V partial column sums (coalesced float4 sweep) ----
        int lane4 = tid & 31;
        int rgrp  = tid >> 5;
        const float4* V4 = (const float4*)(V + base);
        float4 acc4 = make_float4(0.f, 0.f, 0.f, 0.f);
        #pragma unroll 8
        for (int s = s0 + rgrp; s < s0 + CHS; s += 8) {
            float4 v = __ldg(&V4[(size_t)s * 32 + lane4]);
            acc4.x += v.x; acc4.y += v.y; acc4.z += v.z; acc4.w += v.w;
        }
        __shared__ float4 sv[8][32];
        sv[rgrp][lane4] = acc4;
        __syncthreads();
        if (rgrp == 0) {
            float4 t = sv[0][lane4];
            #pragma unroll
            for (int g = 1; g < 8; g++) {
                float4 u = sv[g][lane4];
                t.x += u.x; t.y += u.y; t.z += u.z; t.w += u.w;
            }
            ((float4*)&g_vsum[(bh * NCH + ch) * Dc])[lane4] = t;
        }
        return;
    }

    // ---- top-16 of |Q| + scale (recomputed per block; trivial) ----
    __shared__ float sa[Dc], sqf[Dc];
    __shared__ int   si1[Rc];
    __shared__ float sq[Rc], stop[Rc];
    __shared__ float s_sumAll, s_inv_scale;

    if (tid < Dc) {
        float q = Q[bh * Dc + tid];
        sqf[tid] = q;
        sa[tid]  = fabsf(q);
    }
    __syncthreads();
    if (tid < Dc) {
        float a = sa[tid];
        int rank = 0;
        float sumAll = 0.f;
        #pragma unroll 8
        for (int j = 0; j < Dc; j++) {
            float aj = sa[j];
            sumAll += aj;
            rank += (aj > a) || (aj == a && j < tid);
        }
        if (rank < Rc) { si1[rank] = tid; sq[rank] = sqf[tid]; stop[rank] = a; }
        if (tid == 0) s_sumAll = sumAll;
    }
    __syncthreads();
    if (tid == 0) {
        float st = 0.f;
        #pragma unroll
        for (int j = 0; j < Rc; j++) st += stop[j];
        s_inv_scale = 1.0f / sqrtf((float)Dc * st / s_sumAll);
    }
    __syncthreads();

    const float inv_scale = s_inv_scale;

    // ---- approx logits: one half-warp per row (lanes j=0..15 load si1[j]) ----
    {
        int warp = tid >> 5, lane = tid & 31;
        int half = lane >> 4;
        int j    = lane & 15;
        const int   cidx = si1[j];
        const float qj   = sq[j];
        const float* Kc  = K + base + cidx;
        #pragma unroll
        for (int ot = 0; ot < 4; ot++) {
            float v[8]; int ss[8];
            #pragma unroll
            for (int u = 0; u < 8; u++) {
                int it = ot * 8 + u;
                ss[u] = s0 + (it * 8 + warp) * 2 + half;
                v[u]  = __ldg(Kc + (size_t)ss[u] * Dc);
            }
            #pragma unroll
            for (int u = 0; u < 8; u++) {
                float p = qj * v[u];
                #pragma unroll
                for (int o = 8; o; o >>= 1) p += __shfl_down_sync(~0u, p, o, 16);
                if (j == 0) g_keys[bh * Sc + ss[u]] = f2o(p * inv_scale);
            }
        }
    }
}

// ---------------- kernel CE: top-256 select + alpha + exact attn + combine --
// grid = BH (256) blocks, 1024 threads.
__global__ void __launch_bounds__(1024) kCE(const float* __restrict__ Q,
                                            const float* __restrict__ K,
                                            const float* __restrict__ V,
                                            float* __restrict__ out) {
    int bh   = blockIdx.x;
    int tid  = threadIdx.x;
    int lane = tid & 31, wid = tid >> 5;   // 32 warps

    __shared__ unsigned int keys[Sc];       // 16 KB
    __shared__ float4 sy4[32][32];          // 16 KB
    __shared__ unsigned int hist[256];
    __shared__ int   sel[Ks];
    __shared__ float w[Ks];
    __shared__ float sq[Dc];
    __shared__ float sred[32];
    __shared__ float s_gmax, s_sumexp, s_alpha, s_m, s_ssum;
    __shared__ unsigned int s_prefix;
    __shared__ int s_remaining, cnt, tie_taken, wtot[32];

    if (tid < Dc) sq[tid] = Q[bh * Dc + tid];

    // ---- load ordered keys, block max ----
    unsigned int kmax = 0u;
    #pragma unroll
    for (int i = 0; i < 4; i++) {
        int s = tid + i * 1024;
        unsigned int kk = __ldg(&g_keys[bh * Sc + s]);
        keys[s] = kk;
        kmax = max(kmax, kk);
    }
    #pragma unroll
    for (int o = 16; o; o >>= 1) kmax = max(kmax, __shfl_xor_sync(~0u, kmax, o));
    if (lane == 0) sred[wid] = __uint_as_float(kmax);
    __syncthreads();
    if (tid == 0) {
        unsigned int m = __float_as_uint(sred[0]);
        #pragma unroll
        for (int i = 1; i < 32; i++) m = max(m, __float_as_uint(sred[i]));
        s_gmax = o2f(m);
        s_prefix = 0u; s_remaining = Ks; cnt = 0; tie_taken = 0;
    }
    __syncthreads();
    const float gmax = s_gmax;

    // ---- full sumexp ----
    float lsum = 0.f;
    #pragma unroll
    for (int i = 0; i < 4; i++) lsum += __expf(o2f(keys[tid + i * 1024]) - gmax);
    #pragma unroll
    for (int o = 16; o; o >>= 1) lsum += __shfl_xor_sync(~0u, lsum, o);
    if (lane == 0) sred[wid] = lsum;
    __syncthreads();
    if (tid == 0) {
        float t = 0.f;
        #pragma unroll
        for (int i = 0; i < 32; i++) t += sred[i];
        s_sumexp = t;
    }
    __syncthreads();

    // ---- 4-pass radix select for the 256th-largest key ----
    for (int shift = 24; shift >= 0; shift -= 8) {
        if (tid < 256) hist[tid] = 0u;
        __syncthreads();
        unsigned int pre   = s_prefix;
        unsigned int pmask = (shift == 24) ? 0u : (0xFFFFFFFFu << (shift + 8));
        #pragma unroll
        for (int i = 0; i < 4; i++) {
            unsigned int kk = keys[tid + i * 1024];
            if ((kk & pmask) == pre) atomicAdd(&hist[(kk >> shift) & 0xFFu], 1u);
        }
        __syncthreads();
        if (tid == 0) {
            int rem = s_remaining, dsel = 0;
            for (int dgt = 255; dgt >= 0; dgt--) {
                int c = (int)hist[dgt];
                if (rem <= c) { dsel = dgt; break; }
                rem -= c;
            }
            s_remaining = rem;
            s_prefix = pre | ((unsigned int)dsel << shift);
        }
        __syncthreads();
    }
    const unsigned int T = s_prefix;
    const int need_ties  = s_remaining;
    const int n_greater  = Ks - need_ties;

    // strictly greater (unordered)
    #pragma unroll
    for (int i = 0; i < 4; i++) {
        int s = tid + i * 1024;
        if (keys[s] > T) { int p = atomicAdd(&cnt, 1); sel[p] = s; }
    }
    __syncthreads();
    // ties: deterministic ascending-index compaction
    for (int basei = 0; basei < Sc; basei += 1024) {
        int s = basei + tid;
        bool pred = (keys[s] == T);
        unsigned int bal = __ballot_sync(~0u, pred);
        if (lane == 0) wtot[wid] = __popc(bal);
        __syncthreads();
        int t0 = tie_taken;
        int off = 0, tot = 0;
        #pragma unroll
        for (int wI = 0; wI < 32; wI++) { int c = wtot[wI]; if (wI < wid) off += c; tot += c; }
        if (pred) {
            int rnk = t0 + off + __popc(bal & ((1u << lane) - 1u));
            if (rnk < need_ties) sel[n_greater + rnk] = s;
        }
        __syncthreads();
        if (tid == 0) tie_taken = t0 + tot;
        __syncthreads();
    }

    // ---- alpha = sum_sel exp(l-gmax) / sumexp ----
    float e = (tid < Ks) ? __expf(o2f(keys[sel[tid]]) - gmax) : 0.f;
    #pragma unroll
    for (int o = 16; o; o >>= 1) e += __shfl_xor_sync(~0u, e, o);
    if (lane == 0) sred[wid] = e;
    __syncthreads();
    if (tid == 0) {
        float num = 0.f;
        #pragma unroll
        for (int i = 0; i < 8; i++) num += sred[i];
        s_alpha = num / s_sumexp;
    }
    __syncthreads();

    // ---- exact QK over selected rows: warp w rows {w, w+32, ...}, preloaded ----
    const size_t base = (size_t)bh * Sc * Dc;
    const float inv_sqrtD = 0.08838834764831845f;
    float4 q4 = ((const float4*)sq)[lane];
    {
        float4 kv[8];
        int rs[8];
        #pragma unroll
        for (int rr = 0; rr < 8; rr++) {
            rs[rr] = sel[wid + rr * 32];
            kv[rr] = __ldg(&((const float4*)(K + base + (size_t)rs[rr] * Dc))[lane]);
        }
        #pragma unroll
        for (int rr = 0; rr < 8; rr++) {
            float acc = q4.x * kv[rr].x + q4.y * kv[rr].y + q4.z * kv[rr].z + q4.w * kv[rr].w;
            #pragma unroll
            for (int o = 16; o; o >>= 1) acc += __shfl_xor_sync(~0u, acc, o);
            if (lane == 0) w[wid + rr * 32] = acc * inv_sqrtD;
        }
    }
    __syncthreads();

    // ---- softmax over 256 (threads 0..255) ----
    float m = (tid < Ks) ? w[tid] : -INFINITY;
    #pragma unroll
    for (int o = 16; o; o >>= 1) m = fmaxf(m, __shfl_xor_sync(~0u, m, o));
    if (lane == 0) sred[wid] = m;
    __syncthreads();
    if (tid == 0) {
        float mm = sred[0];
        #pragma unroll
        for (int i = 1; i < 8; i++) mm = fmaxf(mm, sred[i]);
        s_m = mm;
    }
    __syncthreads();
    float ev = (tid < Ks) ? __expf(w[tid] - s_m) : 0.f;
    __syncthreads();
    if (tid < Ks) w[tid] = ev;
    float ls = ev;
    #pragma unroll
    for (int o = 16; o; o >>= 1) ls += __shfl_xor_sync(~0u, ls, o);
    if (lane == 0) sred[wid] = ls;
    __syncthreads();
    if (tid == 0) {
        float t = 0.f;
        #pragma unroll
        for (int i = 0; i < 8; i++) t += sred[i];
        s_ssum = t;
    }
    __syncthreads();

    // ---- y: warp w accumulates rows {w, w+32, ...} in float4 lanes ----
    {
        float4 acc = make_float4(0.f, 0.f, 0.f, 0.f);
        #pragma unroll
        for (int rr = 0; rr < 8; rr++) {
            int r = wid + rr * 32;
            float wr = w[r];
            float4 v = __ldg(&((const float4*)(V + base + (size_t)sel[r] * Dc))[lane]);
            acc.x += wr * v.x; acc.y += wr * v.y; acc.z += wr * v.z; acc.w += wr * v.w;
        }
        sy4[wid][lane] = acc;
    }
    __syncthreads();

    // ---- final combine: 32 threads, each owns one float4 column ----
    if (tid < 32) {
        float4 t = sy4[0][tid];
        #pragma unroll
        for (int g = 1; g < 32; g++) {
            float4 u = sy4[g][tid];
            t.x += u.x; t.y += u.y; t.z += u.z; t.w += u.w;
        }
        float inv_ssum = 1.0f / s_ssum;
        float4 vm = ((const float4*)&g_vsum[bh * NCH * Dc])[tid];
        #pragma unroll
        for (int c = 1; c < NCH; c++) {
            float4 u = ((const float4*)&g_vsum[(bh * NCH + c) * Dc])[tid];
            vm.x += u.x; vm.y += u.y; vm.z += u.z; vm.w += u.w;
        }
        const float invS = 1.0f / (float)Sc;
        float alpha = s_alpha;
        float4 o;
        o.x = vm.x * invS + alpha * (t.x * inv_ssum - vm.x * invS);
        o.y = vm.y * invS + alpha * (t.y * inv_ssum - vm.y * invS);
        o.z = vm.z * invS + alpha * (t.z * inv_ssum - vm.z * invS);
        o.w = vm.w * invS + alpha * (t.w * inv_ssum - vm.w * invS);
        ((float4*)(out + bh * Dc))[tid] = o;
    }
}

// ---------------- launch ----------------------------------------------------
extern "C" void kernel_launch(void* const* d_in, const int* in_sizes, int n_in,
                              void* d_out, int out_size) {
    const float* Q = (const float*)d_in[0];
    const float* K = (const float*)d_in[1];
    const float* V = (const float*)d_in[2];
    float* out = (float*)d_out;

    kB<<<2 * BH * NCH, 256>>>(Q, K, V);
    kCE<<<BH, 1024>>>(Q, K, V, out);
}

// round 9
// speedup vs baseline: 1.8508x; 1.0337x over previous
#include <cuda_runtime.h>
#include <math.h>

// SparQ attention, B=8 H=32 S=4096 D=128 q_len=1 r=16 k=256, mask all-true.
static constexpr int BH  = 256;
static constexpr int Sc  = 4096;
static constexpr int Dc  = 128;
static constexpr int Rc  = 16;
static constexpr int Ks  = 256;
static constexpr int NCH = 8;
static constexpr int CHS = Sc / NCH;   // 512

__device__ unsigned int g_keys[BH * Sc];     // ordered-uint approx logits
__device__ float        g_vsum[BH * NCH * Dc];
__device__ int          g_i1[BH * Rc];
__device__ float        g_qh[BH * Rc];
__device__ float        g_iscale[BH];

__device__ __forceinline__ unsigned int f2o(float f) {
    unsigned int u = __float_as_uint(f);
    return u ^ ((u >> 31) ? 0xFFFFFFFFu : 0x80000000u);
}
__device__ __forceinline__ float o2f(unsigned int k) {
    unsigned int u = k ^ ((k >> 31) ? 0x80000000u : 0xFFFFFFFFu);
    return __uint_as_float(u);
}

// ---------------- kernel A: per-bh top-16(|Q|) + scale ----------------------
__global__ void __launch_bounds__(128) kA(const float* __restrict__ Q) {
    int bh = blockIdx.x;
    int d  = threadIdx.x;          // 128 threads
    __shared__ float sa[Dc], sqf[Dc];
    __shared__ float stop[Rc];
    float q = Q[bh * Dc + d];
    sqf[d] = q;
    sa[d]  = fabsf(q);
    __syncthreads();
    float a = sa[d];
    int rank = 0;
    float sumAll = 0.f;
    #pragma unroll 8
    for (int j = 0; j < Dc; j++) {
        float aj = sa[j];
        sumAll += aj;
        rank += (aj > a) || (aj == a && j < d);   // unique ranks, jax tie order
    }
    if (rank < Rc) {
        g_i1[bh * Rc + rank] = d;
        g_qh[bh * Rc + rank] = q;
        stop[rank] = a;
    }
    __syncthreads();
    if (d == 0) {
        float st = 0.f;
        #pragma unroll
        for (int j = 0; j < Rc; j++) st += stop[j];
        g_iscale[bh] = 1.0f / sqrtf((float)Dc * st / sumAll);
    }
}

// ---------------- kernel B: heterogeneous blocks -----------------------------
// grid = 2*BH*NCH (4096) blocks of 256 threads.
// even blocks: approximate logits for one 512-row chunk (half-warp per row)
// odd  blocks: V partial column sums for one 512-row chunk
__global__ void __launch_bounds__(256) kB(const float* __restrict__ K,
                                          const float* __restrict__ V) {
    int id  = blockIdx.x >> 1;
    int bh  = id >> 3;
    int ch  = id & 7;
    int tid = threadIdx.x;
    const size_t base = (size_t)bh * Sc * Dc;
    const int s0 = ch * CHS;

    if (blockIdx.x & 1) {
        // ---- V partial column sums (coalesced float4 sweep) ----
        int lane4 = tid & 31;
        int rgrp  = tid >> 5;
        const float4* V4 = (const float4*)(V + base);
        float4 acc4 = make_float4(0.f, 0.f, 0.f, 0.f);
        #pragma unroll 8
        for (int s = s0 + rgrp; s < s0 + CHS; s += 8) {
            float4 v = __ldg(&V4[(size_t)s * 32 + lane4]);
            acc4.x += v.x; acc4.y += v.y; acc4.z += v.z; acc4.w += v.w;
        }
        __shared__ float4 sv[8][32];
        sv[rgrp][lane4] = acc4;
        __syncthreads();
        if (rgrp == 0) {
            float4 t = sv[0][lane4];
            #pragma unroll
            for (int g = 1; g < 8; g++) {
                float4 u = sv[g][lane4];
                t.x += u.x; t.y += u.y; t.z += u.z; t.w += u.w;
            }
            ((float4*)&g_vsum[(bh * NCH + ch) * Dc])[lane4] = t;
        }
        return;
    }

    // ---- gather path: load precomputed top-16 ----
    __shared__ int   si1[Rc];
    __shared__ float sq[Rc];
    __shared__ float s_is;
    if (tid < Rc) { si1[tid] = g_i1[bh * Rc + tid]; sq[tid] = g_qh[bh * Rc + tid]; }
    if (tid == 0) s_is = g_iscale[bh];
    __syncthreads();
    const float inv_scale = s_is;

    // one half-warp per row (lanes j=0..15 load column si1[j]); software pipeline
    {
        int warp = tid >> 5, lane = tid & 31;
        int half = lane >> 4;
        int j    = lane & 15;
        const float qj  = sq[j];
        const float* Kc = K + base + si1[j];

        float v[8]; int ss[8];
        #pragma unroll
        for (int u = 0; u < 8; u++) {
            ss[u] = s0 + (u * 8 + warp) * 2 + half;
            v[u]  = __ldg(Kc + (size_t)ss[u] * Dc);
        }
        #pragma unroll
        for (int ot = 0; ot < 4; ot++) {
            float vn[8]; int ssn[8];
            if (ot < 3) {
                #pragma unroll
                for (int u = 0; u < 8; u++) {
                    int it = (ot + 1) * 8 + u;
                    ssn[u] = s0 + (it * 8 + warp) * 2 + half;
                    vn[u]  = __ldg(Kc + (size_t)ssn[u] * Dc);
                }
            }
            #pragma unroll
            for (int u = 0; u < 8; u++) {
                float p = qj * v[u];
                #pragma unroll
                for (int o = 8; o; o >>= 1) p += __shfl_down_sync(~0u, p, o, 16);
                if (j == 0) g_keys[bh * Sc + ss[u]] = f2o(p * inv_scale);
            }
            #pragma unroll
            for (int u = 0; u < 8; u++) { v[u] = vn[u]; ss[u] = ssn[u]; }
        }
    }
}

// ---------------- kernel CE: top-256 select + alpha + flash attn + combine --
// grid = BH (256) blocks, 1024 threads.
__global__ void __launch_bounds__(1024) kCE(const float* __restrict__ Q,
                                            const float* __restrict__ K,
                                            const float* __restrict__ V,
                                            float* __restrict__ out) {
    int bh   = blockIdx.x;
    int tid  = threadIdx.x;
    int lane = tid & 31, wid = tid >> 5;   // 32 warps

    __shared__ unsigned int keys[Sc];       // 16 KB
    __shared__ float4 sy4[32][32];          // 16 KB
    __shared__ unsigned int hist[256];
    __shared__ int   sel[Ks];
    __shared__ float sq[Dc];
    __shared__ float sred[32];
    __shared__ float s_mw[32], s_lw[32];
    __shared__ float s_gmax, s_sumexp, s_alpha;
    __shared__ unsigned int s_prefix;
    __shared__ int s_remaining, cnt, tie_taken, wtot[32];

    if (tid < Dc) sq[tid] = Q[bh * Dc + tid];

    // ---- load ordered keys, block max ----
    unsigned int kmax = 0u;
    #pragma unroll
    for (int i = 0; i < 4; i++) {
        int s = tid + i * 1024;
        unsigned int kk = __ldg(&g_keys[bh * Sc + s]);
        keys[s] = kk;
        kmax = max(kmax, kk);
    }
    #pragma unroll
    for (int o = 16; o; o >>= 1) kmax = max(kmax, __shfl_xor_sync(~0u, kmax, o));
    if (lane == 0) sred[wid] = __uint_as_float(kmax);
    __syncthreads();
    if (tid == 0) {
        unsigned int m = __float_as_uint(sred[0]);
        #pragma unroll
        for (int i = 1; i < 32; i++) m = max(m, __float_as_uint(sred[i]));
        s_gmax = o2f(m);
        s_prefix = 0u; s_remaining = Ks; cnt = 0; tie_taken = 0;
    }
    __syncthreads();
    const float gmax = s_gmax;

    // ---- full sumexp ----
    float lsum = 0.f;
    #pragma unroll
    for (int i = 0; i < 4; i++) lsum += __expf(o2f(keys[tid + i * 1024]) - gmax);
    #pragma unroll
    for (int o = 16; o; o >>= 1) lsum += __shfl_xor_sync(~0u, lsum, o);
    if (lane == 0) sred[wid] = lsum;
    __syncthreads();
    if (tid == 0) {
        float t = 0.f;
        #pragma unroll
        for (int i = 0; i < 32; i++) t += sred[i];
        s_sumexp = t;
    }
    __syncthreads();

    // ---- 4-pass radix select for the 256th-largest key ----
    for (int shift = 24; shift >= 0; shift -= 8) {
        if (tid < 256) hist[tid] = 0u;
        __syncthreads();
        unsigned int pre   = s_prefix;
        unsigned int pmask = (shift == 24) ? 0u : (0xFFFFFFFFu << (shift + 8));
        #pragma unroll
        for (int i = 0; i < 4; i++) {
            unsigned int kk = keys[tid + i * 1024];
            if ((kk & pmask) == pre) atomicAdd(&hist[(kk >> shift) & 0xFFu], 1u);
        }
        __syncthreads();
        // warp-parallel digit scan (warp 0): lane l owns digits [8l, 8l+8)
        if (wid == 0) {
            int h[8]; int psum = 0;
            #pragma unroll
            for (int i = 0; i < 8; i++) { h[i] = (int)hist[8 * lane + i]; psum += h[i]; }
            int rem = s_remaining;
            __syncwarp();
            // inclusive suffix-sum over lanes: S = sum_{l' >= lane} psum
            int S = psum;
            #pragma unroll
            for (int o = 1; o < 32; o <<= 1) {
                int t = __shfl_down_sync(~0u, S, o);
                if (lane + o < 32) S += t;
            }
            int cum = S - psum;   // count of keys in digits >= 8*(lane+1)
            #pragma unroll
            for (int i = 7; i >= 0; i--) {
                int hi = h[i];
                if (rem > cum && rem <= cum + hi) {
                    s_remaining = rem - cum;
                    s_prefix = pre | ((unsigned int)(8 * lane + i) << shift);
                }
                cum += hi;
            }
        }
        __syncthreads();
    }
    const unsigned int T = s_prefix;
    const int need_ties  = s_remaining;
    const int n_greater  = Ks - need_ties;

    // strictly greater (unordered)
    #pragma unroll
    for (int i = 0; i < 4; i++) {
        int s = tid + i * 1024;
        if (keys[s] > T) { int p = atomicAdd(&cnt, 1); sel[p] = s; }
    }
    __syncthreads();
    // ties: deterministic ascending-index compaction
    for (int basei = 0; basei < Sc; basei += 1024) {
        int s = basei + tid;
        bool pred = (keys[s] == T);
        unsigned int bal = __ballot_sync(~0u, pred);
        if (lane == 0) wtot[wid] = __popc(bal);
        __syncthreads();
        int t0 = tie_taken;
        int off = 0, tot = 0;
        #pragma unroll
        for (int wI = 0; wI < 32; wI++) { int c = wtot[wI]; if (wI < wid) off += c; tot += c; }
        if (pred) {
            int rnk = t0 + off + __popc(bal & ((1u << lane) - 1u));
            if (rnk < need_ties) sel[n_greater + rnk] = s;
        }
        __syncthreads();
        if (tid == 0) tie_taken = t0 + tot;
        __syncthreads();
    }

    // ---- alpha = sum_sel exp(l-gmax) / sumexp ----
    float e = (tid < Ks) ? __expf(o2f(keys[sel[tid]]) - gmax) : 0.f;
    #pragma unroll
    for (int o = 16; o; o >>= 1) e += __shfl_xor_sync(~0u, e, o);
    if (lane == 0) sred[wid] = e;
    __syncthreads();
    if (tid == 0) {
        float num = 0.f;
        #pragma unroll
        for (int i = 0; i < 8; i++) num += sred[i];
        s_alpha = num / s_sumexp;
    }

    // ---- flash-style exact attention: warp w owns rows {w, w+32, ...} ----
    // K-row and V-row loaded together, 1-row lookahead; online softmax per warp.
    const size_t base = (size_t)bh * Sc * Dc;
    const float inv_sqrtD = 0.08838834764831845f;
    float4 q4 = ((const float4*)sq)[lane];
    {
        float m_run = -INFINITY, l_run = 0.f;
        float4 acc = make_float4(0.f, 0.f, 0.f, 0.f);

        int r0 = sel[wid];
        float4 kc = __ldg(&((const float4*)(K + base + (size_t)r0 * Dc))[lane]);
        float4 vc = __ldg(&((const float4*)(V + base + (size_t)r0 * Dc))[lane]);

        #pragma unroll
        for (int rr = 0; rr < 8; rr++) {
            float4 kcur = kc, vcur = vc;
            if (rr < 7) {
                int r1 = sel[wid + (rr + 1) * 32];
                kc = __ldg(&((const float4*)(K + base + (size_t)r1 * Dc))[lane]);
                vc = __ldg(&((const float4*)(V + base + (size_t)r1 * Dc))[lane]);
            }
            float qk = q4.x * kcur.x + q4.y * kcur.y + q4.z * kcur.z + q4.w * kcur.w;
            #pragma unroll
            for (int o = 16; o; o >>= 1) qk += __shfl_xor_sync(~0u, qk, o);
            qk *= inv_sqrtD;

            float mn = fmaxf(m_run, qk);
            float sc = __expf(m_run - mn);     // 0 on first iter (m_run = -inf)
            float ev = __expf(qk - mn);
            l_run = l_run * sc + ev;
            acc.x = acc.x * sc + ev * vcur.x;
            acc.y = acc.y * sc + ev * vcur.y;
            acc.z = acc.z * sc + ev * vcur.z;
            acc.w = acc.w * sc + ev * vcur.w;
            m_run = mn;
        }
        if (lane == 0) { s_mw[wid] = m_run; s_lw[wid] = l_run; }
        sy4[wid][lane] = acc;
    }
    __syncthreads();

    // ---- merge 32 warp partials + combine with V_mean (32 threads) ----
    if (tid < 32) {
        float M = s_mw[0];
        #pragma unroll
        for (int g = 1; g < 32; g++) M = fmaxf(M, s_mw[g]);
        float L = 0.f;
        float4 t = make_float4(0.f, 0.f, 0.f, 0.f);
        #pragma unroll
        for (int g = 0; g < 32; g++) {
            float f = __expf(s_mw[g] - M);
            L += s_lw[g] * f;
            float4 u = sy4[g][tid];
            t.x += f * u.x; t.y += f * u.y; t.z += f * u.z; t.w += f * u.w;
        }
        float inv_L = 1.0f / L;

        float4 vm = ((const float4*)&g_vsum[bh * NCH * Dc])[tid];
        #pragma unroll
        for (int c = 1; c < NCH; c++) {
            float4 u = ((const float4*)&g_vsum[(bh * NCH + c) * Dc])[tid];
            vm.x += u.x; vm.y += u.y; vm.z += u.z; vm.w += u.w;
        }
        const float invS = 1.0f / (float)Sc;
        float alpha = s_alpha;
        float4 o;
        o.x = vm.x * invS + alpha * (t.x * inv_L - vm.x * invS);
        o.y = vm.y * invS + alpha * (t.y * inv_L - vm.y * invS);
        o.z = vm.z * invS + alpha * (t.z * inv_L - vm.z * invS);
        o.w = vm.w * invS + alpha * (t.w * inv_L - vm.w * invS);
        ((float4*)(out + bh * Dc))[tid] = o;
    }
}

// ---------------- launch ----------------------------------------------------
extern "C" void kernel_launch(void* const* d_in, const int* in_sizes, int n_in,
                              void* d_out, int out_size) {
    const float* Q = (const float*)d_in[0];
    const float* K = (const float*)d_in[1];
    const float* V = (const float*)d_in[2];
    float* out = (float*)d_out;

    kA<<<BH, 128>>>(Q);
    kB<<<2 * BH * NCH, 256>>>(K, V);
    kCE<<<BH, 1024>>>(Q, K, V, out);
}

// round 10
// speedup vs baseline: 1.8644x; 1.0073x over previous
#include <cuda_runtime.h>
#include <math.h>

// SparQ attention, B=8 H=32 S=4096 D=128 q_len=1 r=16 k=256, mask all-true.
static constexpr int BH  = 256;
static constexpr int Sc  = 4096;
static constexpr int Dc  = 128;
static constexpr int Rc  = 16;
static constexpr int Ks  = 256;
static constexpr int NCH = 8;
static constexpr int CHS = Sc / NCH;   // 512

__device__ unsigned int g_keys[BH * Sc];     // ordered-uint approx logits
__device__ float        g_vsum[BH * NCH * Dc];
__device__ int          g_i1[BH * Rc];
__device__ float        g_qh[BH * Rc];
__device__ float        g_iscale[BH];
__device__ float        g_cm[BH * NCH];      // per-chunk online max of logits
__device__ float        g_cl[BH * NCH];      // per-chunk sum exp(l - m_chunk)
__device__ int          g_sel[BH * Ks];
__device__ float        g_alpha[BH];
__device__ float        g_pm[BH * 4];        // attention partials (4 splits/bh)
__device__ float        g_pl[BH * 4];
__device__ float        g_pacc[BH * 4 * Dc];

__device__ __forceinline__ unsigned int f2o(float f) {
    unsigned int u = __float_as_uint(f);
    return u ^ ((u >> 31) ? 0xFFFFFFFFu : 0x80000000u);
}
__device__ __forceinline__ float o2f(unsigned int k) {
    unsigned int u = k ^ ((k >> 31) ? 0x80000000u : 0xFFFFFFFFu);
    return __uint_as_float(u);
}

// ---------------- kernel A: per-bh top-16(|Q|) + scale ----------------------
__global__ void __launch_bounds__(128) kA(const float* __restrict__ Q) {
    int bh = blockIdx.x;
    int d  = threadIdx.x;          // 128 threads
    __shared__ float sa[Dc], sqf[Dc];
    __shared__ float stop[Rc];
    float q = Q[bh * Dc + d];
    sqf[d] = q;
    sa[d]  = fabsf(q);
    __syncthreads();
    float a = sa[d];
    int rank = 0;
    float sumAll = 0.f;
    #pragma unroll 8
    for (int j = 0; j < Dc; j++) {
        float aj = sa[j];
        sumAll += aj;
        rank += (aj > a) || (aj == a && j < d);   // unique ranks, jax tie order
    }
    if (rank < Rc) {
        g_i1[bh * Rc + rank] = d;
        g_qh[bh * Rc + rank] = q;
        stop[rank] = a;
    }
    __syncthreads();
    if (d == 0) {
        float st = 0.f;
        #pragma unroll
        for (int j = 0; j < Rc; j++) st += stop[j];
        g_iscale[bh] = 1.0f / sqrtf((float)Dc * st / sumAll);
    }
}

// ---------------- kernel B: heterogeneous blocks -----------------------------
// grid = 2*BH*NCH (4096) blocks of 256 threads.
// even blocks: approximate logits for one 512-row chunk + chunk (m,l) partial
// odd  blocks: V partial column sums for one 512-row chunk
__global__ void __launch_bounds__(256) kB(const float* __restrict__ K,
                                          const float* __restrict__ V) {
    int id  = blockIdx.x >> 1;
    int bh  = id >> 3;
    int ch  = id & 7;
    int tid = threadIdx.x;
    const size_t base = (size_t)bh * Sc * Dc;
    const int s0 = ch * CHS;

    if (blockIdx.x & 1) {
        // ---- V partial column sums (coalesced float4 sweep) ----
        int lane4 = tid & 31;
        int rgrp  = tid >> 5;
        const float4* V4 = (const float4*)(V + base);
        float4 acc4 = make_float4(0.f, 0.f, 0.f, 0.f);
        #pragma unroll 8
        for (int s = s0 + rgrp; s < s0 + CHS; s += 8) {
            float4 v = __ldg(&V4[(size_t)s * 32 + lane4]);
            acc4.x += v.x; acc4.y += v.y; acc4.z += v.z; acc4.w += v.w;
        }
        __shared__ float4 sv[8][32];
        sv[rgrp][lane4] = acc4;
        __syncthreads();
        if (rgrp == 0) {
            float4 t = sv[0][lane4];
            #pragma unroll
            for (int g = 1; g < 8; g++) {
                float4 u = sv[g][lane4];
                t.x += u.x; t.y += u.y; t.z += u.z; t.w += u.w;
            }
            ((float4*)&g_vsum[(bh * NCH + ch) * Dc])[lane4] = t;
        }
        return;
    }

    // ---- gather path: load precomputed top-16 ----
    __shared__ int   si1[Rc];
    __shared__ float sq[Rc];
    __shared__ float s_is;
    __shared__ float slog[CHS];     // 2 KB: logits of this chunk
    __shared__ float sred[8];
    __shared__ float s_chm;
    if (tid < Rc) { si1[tid] = g_i1[bh * Rc + tid]; sq[tid] = g_qh[bh * Rc + tid]; }
    if (tid == 0) s_is = g_iscale[bh];
    __syncthreads();
    const float inv_scale = s_is;

    // one half-warp per row (lanes j=0..15 load column si1[j]); software pipeline
    {
        int warp = tid >> 5, lane = tid & 31;
        int half = lane >> 4;
        int j    = lane & 15;
        const float qj  = sq[j];
        const float* Kc = K + base + si1[j];

        float v[8]; int ss[8];
        #pragma unroll
        for (int u = 0; u < 8; u++) {
            ss[u] = s0 + (u * 8 + warp) * 2 + half;
            v[u]  = __ldg(Kc + (size_t)ss[u] * Dc);
        }
        #pragma unroll
        for (int ot = 0; ot < 4; ot++) {
            float vn[8]; int ssn[8];
            if (ot < 3) {
                #pragma unroll
                for (int u = 0; u < 8; u++) {
                    int it = (ot + 1) * 8 + u;
                    ssn[u] = s0 + (it * 8 + warp) * 2 + half;
                    vn[u]  = __ldg(Kc + (size_t)ssn[u] * Dc);
                }
            }
            #pragma unroll
            for (int u = 0; u < 8; u++) {
                float p = qj * v[u];
                #pragma unroll
                for (int o = 8; o; o >>= 1) p += __shfl_down_sync(~0u, p, o, 16);
                if (j == 0) {
                    float lg = p * inv_scale;
                    g_keys[bh * Sc + ss[u]] = f2o(lg);
                    slog[ss[u] - s0] = lg;
                }
            }
            #pragma unroll
            for (int u = 0; u < 8; u++) { v[u] = vn[u]; ss[u] = ssn[u]; }
        }
    }
    __syncthreads();

    // ---- chunk (m, l) partial over the 512 logits ----
    {
        int lane = tid & 31, wid = tid >> 5;
        float m = fmaxf(slog[tid], slog[tid + 256]);
        #pragma unroll
        for (int o = 16; o; o >>= 1) m = fmaxf(m, __shfl_xor_sync(~0u, m, o));
        if (lane == 0) sred[wid] = m;
        __syncthreads();
        if (tid == 0) {
            float mm = sred[0];
            #pragma unroll
            for (int i = 1; i < 8; i++) mm = fmaxf(mm, sred[i]);
            s_chm = mm;
        }
        __syncthreads();
        float M = s_chm;
        float l = __expf(slog[tid] - M) + __expf(slog[tid + 256] - M);
        #pragma unroll
        for (int o = 16; o; o >>= 1) l += __shfl_xor_sync(~0u, l, o);
        if (lane == 0) sred[wid] = l;
        __syncthreads();
        if (tid == 0) {
            float L = 0.f;
            #pragma unroll
            for (int i = 0; i < 8; i++) L += sred[i];
            g_cm[bh * NCH + ch] = M;
            g_cl[bh * NCH + ch] = L;
        }
    }
}

// ---------------- kernel C: top-256 selection + alpha ------------------------
// grid = BH (256) blocks, 512 threads.
__global__ void __launch_bounds__(512) kC() {
    int bh   = blockIdx.x;
    int tid  = threadIdx.x;
    int lane = tid & 31, wid = tid >> 5;   // 16 warps

    __shared__ unsigned int keys[Sc];      // 16 KB
    __shared__ unsigned int hist[256];
    __shared__ int   sel[Ks];
    __shared__ float sred[16];
    __shared__ float s_gmax, s_sumexp;
    __shared__ unsigned int s_prefix;
    __shared__ int s_remaining, cnt, wtot[16];

    // ---- load ordered keys (strided, coalesced) ----
    #pragma unroll
    for (int i = 0; i < 8; i++) {
        int s = tid + i * 512;
        keys[s] = __ldg(&g_keys[bh * Sc + s]);
    }
    if (tid == 0) {
        // gmax + sumexp from the 8 chunk partials (no full-key passes!)
        float M = g_cm[bh * NCH];
        #pragma unroll
        for (int c = 1; c < NCH; c++) M = fmaxf(M, g_cm[bh * NCH + c]);
        float L = 0.f;
        #pragma unroll
        for (int c = 0; c < NCH; c++) L += g_cl[bh * NCH + c] * __expf(g_cm[bh * NCH + c] - M);
        s_gmax = M;
        s_sumexp = L;
        s_prefix = 0u; s_remaining = Ks; cnt = 0;
    }
    __syncthreads();
    const float gmax = s_gmax;

    // ---- 4-pass radix select for the 256th-largest key ----
    for (int shift = 24; shift >= 0; shift -= 8) {
        if (tid < 256) hist[tid] = 0u;
        __syncthreads();
        unsigned int pre   = s_prefix;
        unsigned int pmask = (shift == 24) ? 0u : (0xFFFFFFFFu << (shift + 8));
        #pragma unroll
        for (int i = 0; i < 8; i++) {
            unsigned int kk = keys[tid + i * 512];
            if ((kk & pmask) == pre) atomicAdd(&hist[(kk >> shift) & 0xFFu], 1u);
        }
        __syncthreads();
        // warp-parallel digit scan (warp 0): lane l owns digits [8l, 8l+8)
        if (wid == 0) {
            int h[8]; int psum = 0;
            #pragma unroll
            for (int i = 0; i < 8; i++) { h[i] = (int)hist[8 * lane + i]; psum += h[i]; }
            int rem = s_remaining;
            __syncwarp();
            int S = psum;
            #pragma unroll
            for (int o = 1; o < 32; o <<= 1) {
                int t = __shfl_down_sync(~0u, S, o);
                if (lane + o < 32) S += t;
            }
            int cum = S - psum;   // keys in digits >= 8*(lane+1)
            #pragma unroll
            for (int i = 7; i >= 0; i--) {
                int hi = h[i];
                if (rem > cum && rem <= cum + hi) {
                    s_remaining = rem - cum;
                    s_prefix = pre | ((unsigned int)(8 * lane + i) << shift);
                }
                cum += hi;
            }
        }
        __syncthreads();
    }
    const unsigned int T = s_prefix;
    const int need_ties  = s_remaining;
    const int n_greater  = Ks - need_ties;

    // ---- strictly greater (unordered set) ----
    #pragma unroll
    for (int i = 0; i < 8; i++) {
        int s = tid + i * 512;
        if (keys[s] > T) { int p = atomicAdd(&cnt, 1); sel[p] = s; }
    }
    __syncthreads();

    // ---- ties: single contiguous prefix-scan pass (ascending index) ----
    {
        int base8 = tid * 8;
        int cntT = 0;
        #pragma unroll
        for (int i = 0; i < 8; i++) cntT += (keys[base8 + i] == T) ? 1 : 0;
        int inc = cntT;
        #pragma unroll
        for (int o = 1; o < 32; o <<= 1) {
            int t = __shfl_up_sync(~0u, inc, o);
            if (lane >= o) inc += t;
        }
        if (lane == 31) wtot[wid] = inc;
        __syncthreads();
        if (tid == 0) {
            int run = 0;
            #pragma unroll
            for (int i = 0; i < 16; i++) { int c = wtot[i]; wtot[i] = run; run += c; }
        }
        __syncthreads();
        int rnk = wtot[wid] + inc - cntT;   // exclusive global rank
        #pragma unroll
        for (int i = 0; i < 8; i++) {
            if (keys[base8 + i] == T) {
                if (rnk < need_ties) sel[n_greater + rnk] = base8 + i;
                rnk++;
            }
        }
    }
    __syncthreads();

    // ---- alpha = sum_sel exp(l-gmax) / sumexp ; write sel ----
    float e = (tid < Ks) ? __expf(o2f(keys[sel[tid]]) - gmax) : 0.f;
    #pragma unroll
    for (int o = 16; o; o >>= 1) e += __shfl_xor_sync(~0u, e, o);
    if (lane == 0) sred[wid] = e;
    __syncthreads();
    if (tid == 0) {
        float num = 0.f;
        #pragma unroll
        for (int i = 0; i < 16; i++) num += sred[i];
        g_alpha[bh] = num / s_sumexp;
    }
    if (tid < Ks) g_sel[bh * Ks + tid] = sel[tid];
}

// ---------------- kernel E: flash attention partials (4 splits per bh) ------
// grid = 4*BH (1024) blocks, 128 threads (4 warps x 16 rows each).
__global__ void __launch_bounds__(128) kE(const float* __restrict__ Q,
                                          const float* __restrict__ K,
                                          const float* __restrict__ V) {
    int blk = blockIdx.x;
    int bh  = blk >> 2;
    int p   = blk & 3;
    int tid = threadIdx.x;
    int lane = tid & 31, wid = tid >> 5;

    __shared__ float sq[Dc];
    __shared__ int   ssel[64];
    __shared__ float sm[4], sl[4];
    __shared__ float4 sacc[4][32];

    sq[tid] = Q[bh * Dc + tid];
    if (tid < 64) ssel[tid] = g_sel[bh * Ks + p * 64 + tid];
    __syncthreads();

    const size_t base = (size_t)bh * Sc * Dc;
    const float inv_sqrtD = 0.08838834764831845f;
    float4 q4 = ((const float4*)sq)[lane];

    // warp handles rows ssel[wid*16 .. wid*16+16), lookahead 2
    float m_run = -INFINITY, l_run = 0.f;
    float4 acc = make_float4(0.f, 0.f, 0.f, 0.f);

    float4 kbuf[2], vbuf[2];
    #pragma unroll
    for (int i = 0; i < 2; i++) {
        int r = ssel[wid * 16 + i];
        kbuf[i] = __ldg(&((const float4*)(K + base + (size_t)r * Dc))[lane]);
        vbuf[i] = __ldg(&((const float4*)(V + base + (size_t)r * Dc))[lane]);
    }
    #pragma unroll
    for (int i = 0; i < 16; i++) {
        float4 kc = kbuf[i & 1], vc = vbuf[i & 1];
        if (i + 2 < 16) {
            int r = ssel[wid * 16 + i + 2];
            kbuf[i & 1] = __ldg(&((const float4*)(K + base + (size_t)r * Dc))[lane]);
            vbuf[i & 1] = __ldg(&((const float4*)(V + base + (size_t)r * Dc))[lane]);
        }
        float qk = q4.x * kc.x + q4.y * kc.y + q4.z * kc.z + q4.w * kc.w;
        #pragma unroll
        for (int o = 16; o; o >>= 1) qk += __shfl_xor_sync(~0u, qk, o);
        qk *= inv_sqrtD;

        float mn = fmaxf(m_run, qk);
        float sc = __expf(m_run - mn);
        float ev = __expf(qk - mn);
        l_run = l_run * sc + ev;
        acc.x = acc.x * sc + ev * vc.x;
        acc.y = acc.y * sc + ev * vc.y;
        acc.z = acc.z * sc + ev * vc.z;
        acc.w = acc.w * sc + ev * vc.w;
        m_run = mn;
    }
    if (lane == 0) { sm[wid] = m_run; sl[wid] = l_run; }
    sacc[wid][lane] = acc;
    __syncthreads();

    // warp 0 merges the 4 warp partials -> block partial
    if (wid == 0) {
        float M = fmaxf(fmaxf(sm[0], sm[1]), fmaxf(sm[2], sm[3]));
        float L = 0.f;
        float4 t = make_float4(0.f, 0.f, 0.f, 0.f);
        #pragma unroll
        for (int g = 0; g < 4; g++) {
            float f = __expf(sm[g] - M);
            L += sl[g] * f;
            float4 u = sacc[g][lane];
            t.x += f * u.x; t.y += f * u.y; t.z += f * u.z; t.w += f * u.w;
        }
        if (lane == 0) { g_pm[blk] = M; g_pl[blk] = L; }
        ((float4*)&g_pacc[blk * Dc])[lane] = t;
    }
}

// ---------------- kernel F: combine 4 partials + V_mean + output -------------
// grid = BH (256) blocks, 32 threads.
__global__ void __launch_bounds__(32) kF(float* __restrict__ out) {
    int bh   = blockIdx.x;
    int lane = threadIdx.x;

    float m0 = g_pm[bh * 4 + 0], m1 = g_pm[bh * 4 + 1];
    float m2 = g_pm[bh * 4 + 2], m3 = g_pm[bh * 4 + 3];
    float M = fmaxf(fmaxf(m0, m1), fmaxf(m2, m3));
    float f0 = __expf(m0 - M), f1 = __expf(m1 - M);
    float f2 = __expf(m2 - M), f3 = __expf(m3 - M);
    float L = g_pl[bh * 4 + 0] * f0 + g_pl[bh * 4 + 1] * f1
            + g_pl[bh * 4 + 2] * f2 + g_pl[bh * 4 + 3] * f3;

    float4 a0 = ((const float4*)&g_pacc[(bh * 4 + 0) * Dc])[lane];
    float4 a1 = ((const float4*)&g_pacc[(bh * 4 + 1) * Dc])[lane];
    float4 a2 = ((const float4*)&g_pacc[(bh * 4 + 2) * Dc])[lane];
    float4 a3 = ((const float4*)&g_pacc[(bh * 4 + 3) * Dc])[lane];
    float4 t;
    t.x = f0 * a0.x + f1 * a1.x + f2 * a2.x + f3 * a3.x;
    t.y = f0 * a0.y + f1 * a1.y + f2 * a2.y + f3 * a3.y;
    t.z = f0 * a0.z + f1 * a1.z + f2 * a2.z + f3 * a3.z;
    t.w = f0 * a0.w + f1 * a1.w + f2 * a2.w + f3 * a3.w;
    float inv_L = 1.0f / L;

    float4 vm = ((const float4*)&g_vsum[bh * NCH * Dc])[lane];
    #pragma unroll
    for (int c = 1; c < NCH; c++) {
        float4 u = ((const float4*)&g_vsum[(bh * NCH + c) * Dc])[lane];
        vm.x += u.x; vm.y += u.y; vm.z += u.z; vm.w += u.w;
    }
    const float invS = 1.0f / (float)Sc;
    float alpha = g_alpha[bh];
    float4 o;
    o.x = vm.x * invS + alpha * (t.x * inv_L - vm.x * invS);
    o.y = vm.y * invS + alpha * (t.y * inv_L - vm.y * invS);
    o.z = vm.z * invS + alpha * (t.z * inv_L - vm.z * invS);
    o.w = vm.w * invS + alpha * (t.w * inv_L - vm.w * invS);
    ((float4*)(out + bh * Dc))[lane] = o;
}

// ---------------- launch ----------------------------------------------------
extern "C" void kernel_launch(void* const* d_in, const int* in_sizes, int n_in,
                              void* d_out, int out_size) {
    const float* Q = (const float*)d_in[0];
    const float* K = (const float*)d_in[1];
    const float* V = (const float*)d_in[2];
    float* out = (float*)d_out;

    kA<<<BH, 128>>>(Q);
    kB<<<2 * BH * NCH, 256>>>(K, V);
    kC<<<BH, 512>>>();
    kE<<<4 * BH, 128>>>(Q, K, V);
    kF<<<BH, 32>>>(out);
}

// round 13
// speedup vs baseline: 1.8918x; 1.0147x over previous
#include <cuda_runtime.h>
#include <math.h>

// SparQ attention, B=8 H=32 S=4096 D=128 q_len=1 r=16 k=256, mask all-true.
static constexpr int BH  = 256;
static constexpr int Sc  = 4096;
static constexpr int Dc  = 128;
static constexpr int Rc  = 16;
static constexpr int Ks  = 256;
static constexpr int NCH = 8;
static constexpr int CHS = Sc / NCH;   // 512
static constexpr int NSP = 8;          // attention splits per bh

__device__ unsigned int g_keys[BH * Sc];     // ordered-uint approx logits
__device__ float        g_vsum[BH * NCH * Dc];
__device__ int          g_i1[BH * Rc];
__device__ float        g_qh[BH * Rc];
__device__ float        g_iscale[BH];
__device__ float        g_cm[BH * NCH];      // per-chunk online max of logits
__device__ float        g_cl[BH * NCH];      // per-chunk sum exp(l - m_chunk)
__device__ int          g_sel[BH * Ks];
__device__ float        g_alpha[BH];
__device__ float        g_pm[BH * NSP];      // attention partials
__device__ float        g_pl[BH * NSP];
__device__ float        g_pacc[BH * NSP * Dc];
__device__ int          g_cnt[BH];           // split-completion counters (self-reset)

__device__ __forceinline__ unsigned int f2o(float f) {
    unsigned int u = __float_as_uint(f);
    return u ^ ((u >> 31) ? 0xFFFFFFFFu : 0x80000000u);
}
__device__ __forceinline__ float o2f(unsigned int k) {
    unsigned int u = k ^ ((k >> 31) ? 0x80000000u : 0xFFFFFFFFu);
    return __uint_as_float(u);
}

// ---------------- kernel A: per-bh top-16(|Q|) + scale ----------------------
__global__ void __launch_bounds__(128) kA(const float* __restrict__ Q) {
    int bh = blockIdx.x;
    int d  = threadIdx.x;          // 128 threads
    __shared__ float sa[Dc], sqf[Dc];
    __shared__ float stop[Rc];
    float q = Q[bh * Dc + d];
    sqf[d] = q;
    sa[d]  = fabsf(q);
    __syncthreads();
    float a = sa[d];
    int rank = 0;
    float sumAll = 0.f;
    #pragma unroll 8
    for (int j = 0; j < Dc; j++) {
        float aj = sa[j];
        sumAll += aj;
        rank += (aj > a) || (aj == a && j < d);   // unique ranks, jax tie order
    }
    if (rank < Rc) {
        g_i1[bh * Rc + rank] = d;
        g_qh[bh * Rc + rank] = q;
        stop[rank] = a;
    }
    __syncthreads();
    if (d == 0) {
        float st = 0.f;
        #pragma unroll
        for (int j = 0; j < Rc; j++) st += stop[j];
        g_iscale[bh] = 1.0f / sqrtf((float)Dc * st / sumAll);
    }
}

// ---------------- kernel B: heterogeneous blocks -----------------------------
// grid = 2*BH*NCH (4096) blocks of 256 threads.
// even blocks: approximate logits for one 512-row chunk + chunk (m,l) partial
// odd  blocks: V partial column sums for one 512-row chunk
__global__ void __launch_bounds__(256) kB(const float* __restrict__ K,
                                          const float* __restrict__ V) {
    int id  = blockIdx.x >> 1;
    int bh  = id >> 3;
    int ch  = id & 7;
    int tid = threadIdx.x;
    const size_t base = (size_t)bh * Sc * Dc;
    const int s0 = ch * CHS;

    if (blockIdx.x & 1) {
        // ---- V partial column sums (coalesced float4 sweep) ----
        int lane4 = tid & 31;
        int rgrp  = tid >> 5;
        const float4* V4 = (const float4*)(V + base);
        float4 acc4 = make_float4(0.f, 0.f, 0.f, 0.f);
        #pragma unroll 8
        for (int s = s0 + rgrp; s < s0 + CHS; s += 8) {
            float4 v = __ldg(&V4[(size_t)s * 32 + lane4]);
            acc4.x += v.x; acc4.y += v.y; acc4.z += v.z; acc4.w += v.w;
        }
        __shared__ float4 sv[8][32];
        sv[rgrp][lane4] = acc4;
        __syncthreads();
        if (rgrp == 0) {
            float4 t = sv[0][lane4];
            #pragma unroll
            for (int g = 1; g < 8; g++) {
                float4 u = sv[g][lane4];
                t.x += u.x; t.y += u.y; t.z += u.z; t.w += u.w;
            }
            ((float4*)&g_vsum[(bh * NCH + ch) * Dc])[lane4] = t;
        }
        return;
    }

    // ---- gather path: load precomputed top-16 ----
    __shared__ int   si1[Rc];
    __shared__ float sq[Rc];
    __shared__ float s_is;
    __shared__ float slog[CHS];     // 2 KB: logits of this chunk
    __shared__ float sred[8];
    __shared__ float s_chm;
    if (tid < Rc) { si1[tid] = g_i1[bh * Rc + tid]; sq[tid] = g_qh[bh * Rc + tid]; }
    if (tid == 0) s_is = g_iscale[bh];
    __syncthreads();
    const float inv_scale = s_is;

    // one half-warp per row (lanes j=0..15 load column si1[j]); software pipeline
    {
        int warp = tid >> 5, lane = tid & 31;
        int half = lane >> 4;
        int j    = lane & 15;
        const float qj  = sq[j];
        const float* Kc = K + base + si1[j];

        float v[8]; int ss[8];
        #pragma unroll
        for (int u = 0; u < 8; u++) {
            ss[u] = s0 + (u * 8 + warp) * 2 + half;
            v[u]  = __ldg(Kc + (size_t)ss[u] * Dc);
        }
        #pragma unroll
        for (int ot = 0; ot < 4; ot++) {
            float vn[8]; int ssn[8];
            if (ot < 3) {
                #pragma unroll
                for (int u = 0; u < 8; u++) {
                    int it = (ot + 1) * 8 + u;
                    ssn[u] = s0 + (it * 8 + warp) * 2 + half;
                    vn[u]  = __ldg(Kc + (size_t)ssn[u] * Dc);
                }
            }
            #pragma unroll
            for (int u = 0; u < 8; u++) {
                float p = qj * v[u];
                #pragma unroll
                for (int o = 8; o; o >>= 1) p += __shfl_down_sync(~0u, p, o, 16);
                if (j == 0) {
                    float lg = p * inv_scale;
                    g_keys[bh * Sc + ss[u]] = f2o(lg);
                    slog[ss[u] - s0] = lg;
                }
            }
            #pragma unroll
            for (int u = 0; u < 8; u++) { v[u] = vn[u]; ss[u] = ssn[u]; }
        }
    }
    __syncthreads();

    // ---- chunk (m, l) partial over the 512 logits ----
    {
        int lane = tid & 31, wid = tid >> 5;
        float m = fmaxf(slog[tid], slog[tid + 256]);
        #pragma unroll
        for (int o = 16; o; o >>= 1) m = fmaxf(m, __shfl_xor_sync(~0u, m, o));
        if (lane == 0) sred[wid] = m;
        __syncthreads();
        if (tid == 0) {
            float mm = sred[0];
            #pragma unroll
            for (int i = 1; i < 8; i++) mm = fmaxf(mm, sred[i]);
            s_chm = mm;
        }
        __syncthreads();
        float M = s_chm;
        float l = __expf(slog[tid] - M) + __expf(slog[tid + 256] - M);
        #pragma unroll
        for (int o = 16; o; o >>= 1) l += __shfl_xor_sync(~0u, l, o);
        if (lane == 0) sred[wid] = l;
        __syncthreads();
        if (tid == 0) {
            float L = 0.f;
            #pragma unroll
            for (int i = 0; i < 8; i++) L += sred[i];
            g_cm[bh * NCH + ch] = M;
            g_cl[bh * NCH + ch] = L;
        }
    }
}

// ---------------- kernel C: top-256 selection + alpha (register radix) ------
// grid = BH (256) blocks, 512 threads. Thread t owns keys [8t, 8t+8).
__global__ void __launch_bounds__(512) kC() {
    int bh   = blockIdx.x;
    int tid  = threadIdx.x;
    int lane = tid & 31, wid = tid >> 5;   // 16 warps

    __shared__ unsigned int hist[256];
    __shared__ int   sel[Ks];
    __shared__ float skey[Ks];             // ordered keys of selected rows (as float bits)
    __shared__ float sred[16];
    __shared__ float s_gmax, s_sumexp;
    __shared__ unsigned int s_prefix;
    __shared__ int s_remaining, cnt, wtot[16];

    // ---- load 8 contiguous keys per thread (2x uint4) ----
    unsigned int k0[8];
    {
        const uint4* K4 = (const uint4*)(g_keys + bh * Sc);
        uint4 a = __ldg(&K4[2 * tid]);
        uint4 b = __ldg(&K4[2 * tid + 1]);
        k0[0] = a.x; k0[1] = a.y; k0[2] = a.z; k0[3] = a.w;
        k0[4] = b.x; k0[5] = b.y; k0[6] = b.z; k0[7] = b.w;
    }
    if (tid == 0) {
        float M = g_cm[bh * NCH];
        #pragma unroll
        for (int c = 1; c < NCH; c++) M = fmaxf(M, g_cm[bh * NCH + c]);
        float L = 0.f;
        #pragma unroll
        for (int c = 0; c < NCH; c++) L += g_cl[bh * NCH + c] * __expf(g_cm[bh * NCH + c] - M);
        s_gmax = M;
        s_sumexp = L;
        s_prefix = 0u; s_remaining = Ks; cnt = 0;
    }
    __syncthreads();
    const float gmax = s_gmax;

    // ---- 4-pass radix select for the 256th-largest key (keys in registers) ----
    for (int shift = 24; shift >= 0; shift -= 8) {
        if (tid < 256) hist[tid] = 0u;
        __syncthreads();
        unsigned int pre   = s_prefix;
        unsigned int pmask = (shift == 24) ? 0u : (0xFFFFFFFFu << (shift + 8));
        #pragma unroll
        for (int i = 0; i < 8; i++) {
            if ((k0[i] & pmask) == pre) atomicAdd(&hist[(k0[i] >> shift) & 0xFFu], 1u);
        }
        __syncthreads();
        // warp-parallel digit scan (warp 0): lane l owns digits [8l, 8l+8)
        if (wid == 0) {
            int h[8]; int psum = 0;
            #pragma unroll
            for (int i = 0; i < 8; i++) { h[i] = (int)hist[8 * lane + i]; psum += h[i]; }
            int rem = s_remaining;
            __syncwarp();
            int S = psum;
            #pragma unroll
            for (int o = 1; o < 32; o <<= 1) {
                int t = __shfl_down_sync(~0u, S, o);
                if (lane + o < 32) S += t;
            }
            int cum = S - psum;   // keys in digits >= 8*(lane+1)
            #pragma unroll
            for (int i = 7; i >= 0; i--) {
                int hi = h[i];
                if (rem > cum && rem <= cum + hi) {
                    s_remaining = rem - cum;
                    s_prefix = pre | ((unsigned int)(8 * lane + i) << shift);
                }
                cum += hi;
            }
        }
        __syncthreads();
    }
    const unsigned int T = s_prefix;
    const int need_ties  = s_remaining;
    const int n_greater  = Ks - need_ties;

    // ---- strictly greater (unordered set), write (sel, key) pairs ----
    #pragma unroll
    for (int i = 0; i < 8; i++) {
        if (k0[i] > T) {
            int p = atomicAdd(&cnt, 1);
            sel[p]  = tid * 8 + i;
            skey[p] = __uint_as_float(k0[i]);
        }
    }
    __syncthreads();

    // ---- ties: single contiguous prefix-scan pass (ascending index) ----
    {
        int cntT = 0;
        #pragma unroll
        for (int i = 0; i < 8; i++) cntT += (k0[i] == T) ? 1 : 0;
        int inc = cntT;
        #pragma unroll
        for (int o = 1; o < 32; o <<= 1) {
            int t = __shfl_up_sync(~0u, inc, o);
            if (lane >= o) inc += t;
        }
        if (lane == 31) wtot[wid] = inc;
        __syncthreads();
        if (tid == 0) {
            int run = 0;
            #pragma unroll
            for (int i = 0; i < 16; i++) { int c = wtot[i]; wtot[i] = run; run += c; }
        }
        __syncthreads();
        int rnk = wtot[wid] + inc - cntT;   // exclusive global rank among ties
        #pragma unroll
        for (int i = 0; i < 8; i++) {
            if (k0[i] == T) {
                if (rnk < need_ties) {
                    sel[n_greater + rnk]  = tid * 8 + i;
                    skey[n_greater + rnk] = __uint_as_float(T);
                }
                rnk++;
            }
        }
    }
    __syncthreads();

    // ---- alpha = sum_sel exp(l-gmax) / sumexp ; write sel ----
    float e = (tid < Ks) ? __expf(o2f(__float_as_uint(skey[tid])) - gmax) : 0.f;
    #pragma unroll
    for (int o = 16; o; o >>= 1) e += __shfl_xor_sync(~0u, e, o);
    if (lane == 0) sred[wid] = e;
    __syncthreads();
    if (tid == 0) {
        float num = 0.f;
        #pragma unroll
        for (int i = 0; i < 16; i++) num += sred[i];
        g_alpha[bh] = num / s_sumexp;
    }
    if (tid < Ks) g_sel[bh * Ks + tid] = sel[tid];
}

// ---------------- kernel E: flash attention partials + fused combine --------
// grid = NSP*BH (2048) blocks, 128 threads (4 warps x 8 rows each).
// Last-finishing split per bh performs the combine (split-K fixup).
__global__ void __launch_bounds__(128) kE(const float* __restrict__ Q,
                                          const float* __restrict__ K,
                                          const float* __restrict__ V,
                                          float* __restrict__ out) {
    int blk = blockIdx.x;
    int bh  = blk >> 3;
    int p   = blk & (NSP - 1);
    int tid = threadIdx.x;
    int lane = tid & 31, wid = tid >> 5;

    __shared__ float sq[Dc];
    __shared__ int   ssel[Ks / NSP];      // 32
    __shared__ float sm[4], sl[4];
    __shared__ float4 sacc[4][32];

    sq[tid] = Q[bh * Dc + tid];
    if (tid < Ks / NSP) ssel[tid] = g_sel[bh * Ks + p * (Ks / NSP) + tid];
    __syncthreads();

    const size_t base = (size_t)bh * Sc * Dc;
    const float inv_sqrtD = 0.08838834764831845f;
    float4 q4 = ((const float4*)sq)[lane];

    // warp handles rows ssel[wid*8 .. wid*8+8), lookahead 2
    float m_run = -INFINITY, l_run = 0.f;
    float4 acc = make_float4(0.f, 0.f, 0.f, 0.f);

    float4 kbuf[2], vbuf[2];
    #pragma unroll
    for (int i = 0; i < 2; i++) {
        int r = ssel[wid * 8 + i];
        kbuf[i] = __ldg(&((const float4*)(K + base + (size_t)r * Dc))[lane]);
        vbuf[i] = __ldg(&((const float4*)(V + base + (size_t)r * Dc))[lane]);
    }
    #pragma unroll
    for (int i = 0; i < 8; i++) {
        float4 kc = kbuf[i & 1], vc = vbuf[i & 1];
        if (i + 2 < 8) {
            int r = ssel[wid * 8 + i + 2];
            kbuf[i & 1] = __ldg(&((const float4*)(K + base + (size_t)r * Dc))[lane]);
            vbuf[i & 1] = __ldg(&((const float4*)(V + base + (size_t)r * Dc))[lane]);
        }
        float qk = q4.x * kc.x + q4.y * kc.y + q4.z * kc.z + q4.w * kc.w;
        #pragma unroll
        for (int o = 16; o; o >>= 1) qk += __shfl_xor_sync(~0u, qk, o);
        qk *= inv_sqrtD;

        float mn = fmaxf(m_run, qk);
        float sc = __expf(m_run - mn);
        float ev = __expf(qk - mn);
        l_run = l_run * sc + ev;
        acc.x = acc.x * sc + ev * vc.x;
        acc.y = acc.y * sc + ev * vc.y;
        acc.z = acc.z * sc + ev * vc.z;
        acc.w = acc.w * sc + ev * vc.w;
        m_run = mn;
    }
    if (lane == 0) { sm[wid] = m_run; sl[wid] = l_run; }
    sacc[wid][lane] = acc;
    __syncthreads();

    // warp 0: merge 4 warp partials -> block partial, then maybe combine
    if (wid == 0) {
        float M = fmaxf(fmaxf(sm[0], sm[1]), fmaxf(sm[2], sm[3]));
        float L = 0.f;
        float4 t = make_float4(0.f, 0.f, 0.f, 0.f);
        #pragma unroll
        for (int g = 0; g < 4; g++) {
            float f = __expf(sm[g] - M);
            L += sl[g] * f;
            float4 u = sacc[g][lane];
            t.x += f * u.x; t.y += f * u.y; t.z += f * u.z; t.w += f * u.w;
        }
        if (lane == 0) { g_pm[blk] = M; g_pl[blk] = L; }
        ((float4*)&g_pacc[blk * Dc])[lane] = t;
        __threadfence();

        int old = 0;
        if (lane == 0) old = atomicAdd(&g_cnt[bh], 1);
        old = __shfl_sync(~0u, old, 0);

        if (old == NSP - 1) {
            __threadfence();
            // combine NSP split partials
            float ms[NSP];
            #pragma unroll
            for (int s = 0; s < NSP; s++) ms[s] = __ldcg(&g_pm[bh * NSP + s]);
            float MM = ms[0];
            #pragma unroll
            for (int s = 1; s < NSP; s++) MM = fmaxf(MM, ms[s]);
            float LL = 0.f;
            float4 tt = make_float4(0.f, 0.f, 0.f, 0.f);
            #pragma unroll
            for (int s = 0; s < NSP; s++) {
                float f = __expf(ms[s] - MM);
                LL += __ldcg(&g_pl[bh * NSP + s]) * f;
                float4 u = __ldcg(&((const float4*)&g_pacc[(bh * NSP + s) * Dc])[lane]);
                tt.x += f * u.x; tt.y += f * u.y; tt.z += f * u.z; tt.w += f * u.w;
            }
            float inv_L = 1.0f / LL;

            float4 vm = ((const float4*)&g_vsum[bh * NCH * Dc])[lane];
            #pragma unroll
            for (int c = 1; c < NCH; c++) {
                float4 u = ((const float4*)&g_vsum[(bh * NCH + c) * Dc])[lane];
                vm.x += u.x; vm.y += u.y; vm.z += u.z; vm.w += u.w;
            }
            const float invS = 1.0f / (float)Sc;
            float alpha = g_alpha[bh];
            float4 o;
            o.x = vm.x * invS + alpha * (tt.x * inv_L - vm.x * invS);
            o.y = vm.y * invS + alpha * (tt.y * inv_L - vm.y * invS);
            o.z = vm.z * invS + alpha * (tt.z * inv_L - vm.z * invS);
            o.w = vm.w * invS + alpha * (tt.w * inv_L - vm.w * invS);
            ((float4*)(out + bh * Dc))[lane] = o;

            if (lane == 0) g_cnt[bh] = 0;   // reset for next graph replay
        }
    }
}

// ---------------- launch ----------------------------------------------------
extern "C" void kernel_launch(void* const* d_in, const int* in_sizes, int n_in,
                              void* d_out, int out_size) {
    const float* Q = (const float*)d_in[0];
    const float* K = (const float*)d_in[1];
    const float* V = (const float*)d_in[2];
    float* out = (float*)d_out;

    kA<<<BH, 128>>>(Q);
    kB<<<2 * BH * NCH, 256>>>(K, V);
    kC<<<BH, 512>>>();
    kE<<<NSP * BH, 128>>>(Q, K, V, out);
}

// round 14
// speedup vs baseline: 1.8967x; 1.0026x over previous
#include <cuda_runtime.h>
#include <math.h>

// SparQ attention, B=8 H=32 S=4096 D=128 q_len=1 r=16 k=256, mask all-true.
static constexpr int BH  = 256;
static constexpr int Sc  = 4096;
static constexpr int Dc  = 128;
static constexpr int Rc  = 16;
static constexpr int Ks  = 256;
static constexpr int NCH = 8;
static constexpr int CHS = Sc / NCH;   // 512
static constexpr int NSP = 4;          // attention splits per bh
static constexpr int RPW = Ks / NSP / 4;  // rows per warp = 16

__device__ unsigned int g_keys[BH * Sc];     // ordered-uint approx logits
__device__ float        g_vsum[BH * NCH * Dc];
__device__ int          g_i1[BH * Rc];
__device__ float        g_qh[BH * Rc];
__device__ float        g_iscale[BH];
__device__ float        g_cm[BH * NCH];      // per-chunk online max of logits
__device__ float        g_cl[BH * NCH];      // per-chunk sum exp(l - m_chunk)
__device__ int          g_sel[BH * Ks];
__device__ float        g_alpha[BH];
__device__ float        g_pm[BH * NSP];      // attention partials
__device__ float        g_pl[BH * NSP];
__device__ float        g_pacc[BH * NSP * Dc];
__device__ int          g_cnt[BH];           // split-completion counters (self-reset)

__device__ __forceinline__ unsigned int f2o(float f) {
    unsigned int u = __float_as_uint(f);
    return u ^ ((u >> 31) ? 0xFFFFFFFFu : 0x80000000u);
}
__device__ __forceinline__ float o2f(unsigned int k) {
    unsigned int u = k ^ ((k >> 31) ? 0x80000000u : 0xFFFFFFFFu);
    return __uint_as_float(u);
}

// ---------------- kernel A: per-bh top-16(|Q|) + scale ----------------------
__global__ void __launch_bounds__(128) kA(const float* __restrict__ Q) {
    int bh = blockIdx.x;
    int d  = threadIdx.x;          // 128 threads
    __shared__ float sa[Dc], sqf[Dc];
    __shared__ float stop[Rc];
    float q = Q[bh * Dc + d];
    sqf[d] = q;
    sa[d]  = fabsf(q);
    __syncthreads();
    float a = sa[d];
    int rank = 0;
    float sumAll = 0.f;
    #pragma unroll 8
    for (int j = 0; j < Dc; j++) {
        float aj = sa[j];
        sumAll += aj;
        rank += (aj > a) || (aj == a && j < d);   // unique ranks, jax tie order
    }
    if (rank < Rc) {
        g_i1[bh * Rc + rank] = d;
        g_qh[bh * Rc + rank] = q;
        stop[rank] = a;
    }
    __syncthreads();
    if (d == 0) {
        float st = 0.f;
        #pragma unroll
        for (int j = 0; j < Rc; j++) st += stop[j];
        g_iscale[bh] = 1.0f / sqrtf((float)Dc * st / sumAll);
    }
}

// ---------------- kernel B: heterogeneous blocks -----------------------------
// grid = 2*BH*NCH (4096) blocks of 256 threads.
// even blocks: approximate logits for one 512-row chunk + chunk (m,l) partial
// odd  blocks: V partial column sums for one 512-row chunk
__global__ void __launch_bounds__(256) kB(const float* __restrict__ K,
                                          const float* __restrict__ V) {
    int id  = blockIdx.x >> 1;
    int bh  = id >> 3;
    int ch  = id & 7;
    int tid = threadIdx.x;
    const size_t base = (size_t)bh * Sc * Dc;
    const int s0 = ch * CHS;

    if (blockIdx.x & 1) {
        // ---- V partial column sums (coalesced float4 sweep) ----
        int lane4 = tid & 31;
        int rgrp  = tid >> 5;
        const float4* V4 = (const float4*)(V + base);
        float4 acc4 = make_float4(0.f, 0.f, 0.f, 0.f);
        #pragma unroll 8
        for (int s = s0 + rgrp; s < s0 + CHS; s += 8) {
            float4 v = __ldg(&V4[(size_t)s * 32 + lane4]);
            acc4.x += v.x; acc4.y += v.y; acc4.z += v.z; acc4.w += v.w;
        }
        __shared__ float4 sv[8][32];
        sv[rgrp][lane4] = acc4;
        __syncthreads();
        if (rgrp == 0) {
            float4 t = sv[0][lane4];
            #pragma unroll
            for (int g = 1; g < 8; g++) {
                float4 u = sv[g][lane4];
                t.x += u.x; t.y += u.y; t.z += u.z; t.w += u.w;
            }
            ((float4*)&g_vsum[(bh * NCH + ch) * Dc])[lane4] = t;
        }
        return;
    }

    // ---- gather path: load precomputed top-16 ----
    __shared__ int   si1[Rc];
    __shared__ float sq[Rc];
    __shared__ float s_is;
    __shared__ float slog[CHS];     // 2 KB: logits of this chunk
    __shared__ float sred[8];
    __shared__ float s_chm;
    if (tid < Rc) { si1[tid] = g_i1[bh * Rc + tid]; sq[tid] = g_qh[bh * Rc + tid]; }
    if (tid == 0) s_is = g_iscale[bh];
    __syncthreads();
    const float inv_scale = s_is;

    // one half-warp per row (lanes j=0..15 load column si1[j]); software pipeline
    {
        int warp = tid >> 5, lane = tid & 31;
        int half = lane >> 4;
        int j    = lane & 15;
        const float qj  = sq[j];
        const float* Kc = K + base + si1[j];

        float v[8]; int ss[8];
        #pragma unroll
        for (int u = 0; u < 8; u++) {
            ss[u] = s0 + (u * 8 + warp) * 2 + half;
            v[u]  = __ldg(Kc + (size_t)ss[u] * Dc);
        }
        #pragma unroll
        for (int ot = 0; ot < 4; ot++) {
            float vn[8]; int ssn[8];
            if (ot < 3) {
                #pragma unroll
                for (int u = 0; u < 8; u++) {
                    int it = (ot + 1) * 8 + u;
                    ssn[u] = s0 + (it * 8 + warp) * 2 + half;
                    vn[u]  = __ldg(Kc + (size_t)ssn[u] * Dc);
                }
            }
            #pragma unroll
            for (int u = 0; u < 8; u++) {
                float p = qj * v[u];
                #pragma unroll
                for (int o = 8; o; o >>= 1) p += __shfl_down_sync(~0u, p, o, 16);
                if (j == 0) {
                    float lg = p * inv_scale;
                    g_keys[bh * Sc + ss[u]] = f2o(lg);
                    slog[ss[u] - s0] = lg;
                }
            }
            #pragma unroll
            for (int u = 0; u < 8; u++) { v[u] = vn[u]; ss[u] = ssn[u]; }
        }
    }
    __syncthreads();

    // ---- chunk (m, l) partial over the 512 logits ----
    {
        int lane = tid & 31, wid = tid >> 5;
        float m = fmaxf(slog[tid], slog[tid + 256]);
        #pragma unroll
        for (int o = 16; o; o >>= 1) m = fmaxf(m, __shfl_xor_sync(~0u, m, o));
        if (lane == 0) sred[wid] = m;
        __syncthreads();
        if (tid == 0) {
            float mm = sred[0];
            #pragma unroll
            for (int i = 1; i < 8; i++) mm = fmaxf(mm, sred[i]);
            s_chm = mm;
        }
        __syncthreads();
        float M = s_chm;
        float l = __expf(slog[tid] - M) + __expf(slog[tid + 256] - M);
        #pragma unroll
        for (int o = 16; o; o >>= 1) l += __shfl_xor_sync(~0u, l, o);
        if (lane == 0) sred[wid] = l;
        __syncthreads();
        if (tid == 0) {
            float L = 0.f;
            #pragma unroll
            for (int i = 0; i < 8; i++) L += sred[i];
            g_cm[bh * NCH + ch] = M;
            g_cl[bh * NCH + ch] = L;
        }
    }
}

// ---------------- kernel C: top-256 selection + alpha (register radix) ------
// grid = BH (256) blocks, 512 threads. Thread t owns keys [8t, 8t+8).
__global__ void __launch_bounds__(512) kC() {
    int bh   = blockIdx.x;
    int tid  = threadIdx.x;
    int lane = tid & 31, wid = tid >> 5;   // 16 warps

    __shared__ unsigned int hist[256];
    __shared__ int   sel[Ks];
    __shared__ float skey[Ks];             // ordered keys of selected rows (as float bits)
    __shared__ float sred[16];
    __shared__ float s_gmax, s_sumexp;
    __shared__ unsigned int s_prefix;
    __shared__ int s_remaining, cnt, wtot[16];

    // ---- load 8 contiguous keys per thread (2x uint4) ----
    unsigned int k0[8];
    {
        const uint4* K4 = (const uint4*)(g_keys + bh * Sc);
        uint4 a = __ldg(&K4[2 * tid]);
        uint4 b = __ldg(&K4[2 * tid + 1]);
        k0[0] = a.x; k0[1] = a.y; k0[2] = a.z; k0[3] = a.w;
        k0[4] = b.x; k0[5] = b.y; k0[6] = b.z; k0[7] = b.w;
    }
    if (tid == 0) {
        float M = g_cm[bh * NCH];
        #pragma unroll
        for (int c = 1; c < NCH; c++) M = fmaxf(M, g_cm[bh * NCH + c]);
        float L = 0.f;
        #pragma unroll
        for (int c = 0; c < NCH; c++) L += g_cl[bh * NCH + c] * __expf(g_cm[bh * NCH + c] - M);
        s_gmax = M;
        s_sumexp = L;
        s_prefix = 0u; s_remaining = Ks; cnt = 0;
    }
    __syncthreads();
    const float gmax = s_gmax;

    // ---- 4-pass radix select for the 256th-largest key (keys in registers) ----
    for (int shift = 24; shift >= 0; shift -= 8) {
        if (tid < 256) hist[tid] = 0u;
        __syncthreads();
        unsigned int pre   = s_prefix;
        unsigned int pmask = (shift == 24) ? 0u : (0xFFFFFFFFu << (shift + 8));
        #pragma unroll
        for (int i = 0; i < 8; i++) {
            if ((k0[i] & pmask) == pre) atomicAdd(&hist[(k0[i] >> shift) & 0xFFu], 1u);
        }
        __syncthreads();
        // warp-parallel digit scan (warp 0): lane l owns digits [8l, 8l+8)
        if (wid == 0) {
            int h[8]; int psum = 0;
            #pragma unroll
            for (int i = 0; i < 8; i++) { h[i] = (int)hist[8 * lane + i]; psum += h[i]; }
            int rem = s_remaining;
            __syncwarp();
            int S = psum;
            #pragma unroll
            for (int o = 1; o < 32; o <<= 1) {
                int t = __shfl_down_sync(~0u, S, o);
                if (lane + o < 32) S += t;
            }
            int cum = S - psum;   // keys in digits >= 8*(lane+1)
            #pragma unroll
            for (int i = 7; i >= 0; i--) {
                int hi = h[i];
                if (rem > cum && rem <= cum + hi) {
                    s_remaining = rem - cum;
                    s_prefix = pre | ((unsigned int)(8 * lane + i) << shift);
                }
                cum += hi;
            }
        }
        __syncthreads();
    }
    const unsigned int T = s_prefix;
    const int need_ties  = s_remaining;
    const int n_greater  = Ks - need_ties;

    // ---- strictly greater (unordered set), write (sel, key) pairs ----
    #pragma unroll
    for (int i = 0; i < 8; i++) {
        if (k0[i] > T) {
            int p = atomicAdd(&cnt, 1);
            sel[p]  = tid * 8 + i;
            skey[p] = __uint_as_float(k0[i]);
        }
    }
    __syncthreads();

    // ---- ties: single contiguous prefix-scan pass (ascending index) ----
    {
        int cntT = 0;
        #pragma unroll
        for (int i = 0; i < 8; i++) cntT += (k0[i] == T) ? 1 : 0;
        int inc = cntT;
        #pragma unroll
        for (int o = 1; o < 32; o <<= 1) {
            int t = __shfl_up_sync(~0u, inc, o);
            if (lane >= o) inc += t;
        }
        if (lane == 31) wtot[wid] = inc;
        __syncthreads();
        if (tid == 0) {
            int run = 0;
            #pragma unroll
            for (int i = 0; i < 16; i++) { int c = wtot[i]; wtot[i] = run; run += c; }
        }
        __syncthreads();
        int rnk = wtot[wid] + inc - cntT;   // exclusive global rank among ties
        #pragma unroll
        for (int i = 0; i < 8; i++) {
            if (k0[i] == T) {
                if (rnk < need_ties) {
                    sel[n_greater + rnk]  = tid * 8 + i;
                    skey[n_greater + rnk] = __uint_as_float(T);
                }
                rnk++;
            }
        }
    }
    __syncthreads();

    // ---- alpha = sum_sel exp(l-gmax) / sumexp ; write sel ----
    float e = (tid < Ks) ? __expf(o2f(__float_as_uint(skey[tid])) - gmax) : 0.f;
    #pragma unroll
    for (int o = 16; o; o >>= 1) e += __shfl_xor_sync(~0u, e, o);
    if (lane == 0) sred[wid] = e;
    __syncthreads();
    if (tid == 0) {
        float num = 0.f;
        #pragma unroll
        for (int i = 0; i < 16; i++) num += sred[i];
        g_alpha[bh] = num / s_sumexp;
    }
    if (tid < Ks) g_sel[bh * Ks + tid] = sel[tid];
}

// ---------------- kernel E: flash attention partials + fused combine --------
// grid = NSP*BH (1024) blocks, 128 threads (4 warps x 16 rows, lookahead 4).
// Last-finishing split per bh performs the combine (split-K fixup).
__global__ void __launch_bounds__(128) kE(const float* __restrict__ Q,
                                          const float* __restrict__ K,
                                          const float* __restrict__ V,
                                          float* __restrict__ out) {
    int blk = blockIdx.x;
    int bh  = blk >> 2;
    int p   = blk & (NSP - 1);
    int tid = threadIdx.x;
    int lane = tid & 31, wid = tid >> 5;

    __shared__ float sq[Dc];
    __shared__ int   ssel[Ks / NSP];      // 64
    __shared__ float sm[4], sl[4];
    __shared__ float4 sacc[4][32];

    sq[tid] = Q[bh * Dc + tid];
    if (tid < Ks / NSP) ssel[tid] = g_sel[bh * Ks + p * (Ks / NSP) + tid];
    __syncthreads();

    const size_t base = (size_t)bh * Sc * Dc;
    const float inv_sqrtD = 0.08838834764831845f;
    float4 q4 = ((const float4*)sq)[lane];

    // warp handles rows ssel[wid*16 .. wid*16+16), lookahead 4
    float m_run = -INFINITY, l_run = 0.f;
    float4 acc = make_float4(0.f, 0.f, 0.f, 0.f);

    float4 kbuf[4], vbuf[4];
    #pragma unroll
    for (int i = 0; i < 4; i++) {
        int r = ssel[wid * RPW + i];
        kbuf[i] = __ldg(&((const float4*)(K + base + (size_t)r * Dc))[lane]);
        vbuf[i] = __ldg(&((const float4*)(V + base + (size_t)r * Dc))[lane]);
    }
    #pragma unroll
    for (int i = 0; i < RPW; i++) {
        float4 kc = kbuf[i & 3], vc = vbuf[i & 3];
        if (i + 4 < RPW) {
            int r = ssel[wid * RPW + i + 4];
            kbuf[i & 3] = __ldg(&((const float4*)(K + base + (size_t)r * Dc))[lane]);
            vbuf[i & 3] = __ldg(&((const float4*)(V + base + (size_t)r * Dc))[lane]);
        }
        float qk = q4.x * kc.x + q4.y * kc.y + q4.z * kc.z + q4.w * kc.w;
        #pragma unroll
        for (int o = 16; o; o >>= 1) qk += __shfl_xor_sync(~0u, qk, o);
        qk *= inv_sqrtD;

        float mn = fmaxf(m_run, qk);
        float sc = __expf(m_run - mn);
        float ev = __expf(qk - mn);
        l_run = l_run * sc + ev;
        acc.x = acc.x * sc + ev * vc.x;
        acc.y = acc.y * sc + ev * vc.y;
        acc.z = acc.z * sc + ev * vc.z;
        acc.w = acc.w * sc + ev * vc.w;
        m_run = mn;
    }
    if (lane == 0) { sm[wid] = m_run; sl[wid] = l_run; }
    sacc[wid][lane] = acc;
    __syncthreads();

    // warp 0: merge 4 warp partials -> block partial, then maybe combine
    if (wid == 0) {
        float M = fmaxf(fmaxf(sm[0], sm[1]), fmaxf(sm[2], sm[3]));
        float L = 0.f;
        float4 t = make_float4(0.f, 0.f, 0.f, 0.f);
        #pragma unroll
        for (int g = 0; g < 4; g++) {
            float f = __expf(sm[g] - M);
            L += sl[g] * f;
            float4 u = sacc[g][lane];
            t.x += f * u.x; t.y += f * u.y; t.z += f * u.z; t.w += f * u.w;
        }
        if (lane == 0) { g_pm[blk] = M; g_pl[blk] = L; }
        ((float4*)&g_pacc[blk * Dc])[lane] = t;
        __threadfence();

        int old = 0;
        if (lane == 0) old = atomicAdd(&g_cnt[bh], 1);
        old = __shfl_sync(~0u, old, 0);

        if (old == NSP - 1) {
            __threadfence();
            // combine NSP split partials
            float ms[NSP];
            #pragma unroll
            for (int s = 0; s < NSP; s++) ms[s] = __ldcg(&g_pm[bh * NSP + s]);
            float MM = ms[0];
            #pragma unroll
            for (int s = 1; s < NSP; s++) MM = fmaxf(MM, ms[s]);
            float LL = 0.f;
            float4 tt = make_float4(0.f, 0.f, 0.f, 0.f);
            #pragma unroll
            for (int s = 0; s < NSP; s++) {
                float f = __expf(ms[s] - MM);
                LL += __ldcg(&g_pl[bh * NSP + s]) * f;
                float4 u = __ldcg(&((const float4*)&g_pacc[(bh * NSP + s) * Dc])[lane]);
                tt.x += f * u.x; tt.y += f * u.y; tt.z += f * u.z; tt.w += f * u.w;
            }
            float inv_L = 1.0f / LL;

            float4 vm = ((const float4*)&g_vsum[bh * NCH * Dc])[lane];
            #pragma unroll
            for (int c = 1; c < NCH; c++) {
                float4 u = ((const float4*)&g_vsum[(bh * NCH + c) * Dc])[lane];
                vm.x += u.x; vm.y += u.y; vm.z += u.z; vm.w += u.w;
            }
            const float invS = 1.0f / (float)Sc;
            float alpha = g_alpha[bh];
            float4 o;
            o.x = vm.x * invS + alpha * (tt.x * inv_L - vm.x * invS);
            o.y = vm.y * invS + alpha * (tt.y * inv_L - vm.y * invS);
            o.z = vm.z * invS + alpha * (tt.z * inv_L - vm.z * invS);
            o.w = vm.w * invS + alpha * (tt.w * inv_L - vm.w * invS);
            ((float4*)(out + bh * Dc))[lane] = o;

            if (lane == 0) g_cnt[bh] = 0;   // reset for next graph replay
        }
    }
}

// ---------------- launch ----------------------------------------------------
extern "C" void kernel_launch(void* const* d_in, const int* in_sizes, int n_in,
                              void* d_out, int out_size) {
    const float* Q = (const float*)d_in[0];
    const float* K = (const float*)d_in[1];
    const float* V = (const float*)d_in[2];
    float* out = (float*)d_out;

    kA<<<BH, 128>>>(Q);
    kB<<<2 * BH * NCH, 256>>>(K, V);
    kC<<<BH, 512>>>();
    kE<<<NSP * BH, 128>>>(Q, K, V, out);
}

// round 16
// speedup vs baseline: 1.9474x; 1.0267x over previous
#include <cuda_runtime.h>
#include <math.h>

// SparQ attention, B=8 H=32 S=4096 D=128 q_len=1 r=16 k=256, mask all-true.
static constexpr int BH  = 256;
static constexpr int Sc  = 4096;
static constexpr int Dc  = 128;
static constexpr int Rc  = 16;
static constexpr int Ks  = 256;
static constexpr int NCH = 8;
static constexpr int CHS = Sc / NCH;   // 512
static constexpr int NSP = 4;          // attention splits per bh
static constexpr int RPW = Ks / NSP / 4;  // rows per warp = 16

__device__ unsigned int g_keys[BH * Sc];     // ordered-uint approx logits
__device__ float        g_vsum[BH * NCH * Dc];
__device__ int          g_i1[BH * Rc];
__device__ float        g_qh[BH * Rc];
__device__ float        g_iscale[BH];
__device__ float        g_cm[BH * NCH];      // per-chunk online max of logits
__device__ float        g_cl[BH * NCH];      // per-chunk sum exp(l - m_chunk)
__device__ int          g_sel[BH * Ks];
__device__ float        g_alpha[BH];
__device__ float        g_pm[BH * NSP];      // attention partials
__device__ float        g_pl[BH * NSP];
__device__ float        g_pacc[BH * NSP * Dc];
__device__ int          g_cnt[BH];           // split-completion counters (self-reset)

__device__ __forceinline__ unsigned int f2o(float f) {
    unsigned int u = __float_as_uint(f);
    return u ^ ((u >> 31) ? 0xFFFFFFFFu : 0x80000000u);
}
__device__ __forceinline__ float o2f(unsigned int k) {
    unsigned int u = k ^ ((k >> 31) ? 0x80000000u : 0xFFFFFFFFu);
    return __uint_as_float(u);
}

// ---------------- kernel A: per-bh top-16(|Q|) + scale ----------------------
__global__ void __launch_bounds__(128) kA(const float* __restrict__ Q) {
    int bh = blockIdx.x;
    int d  = threadIdx.x;          // 128 threads
    __shared__ float sa[Dc], sqf[Dc];
    __shared__ float stop[Rc];
    float q = Q[bh * Dc + d];
    sqf[d] = q;
    sa[d]  = fabsf(q);
    __syncthreads();
    float a = sa[d];
    int rank = 0;
    float sumAll = 0.f;
    #pragma unroll 8
    for (int j = 0; j < Dc; j++) {
        float aj = sa[j];
        sumAll += aj;
        rank += (aj > a) || (aj == a && j < d);   // unique ranks, jax tie order
    }
    if (rank < Rc) {
        g_i1[bh * Rc + rank] = d;
        g_qh[bh * Rc + rank] = q;
        stop[rank] = a;
    }
    __syncthreads();
    if (d == 0) {
        float st = 0.f;
        #pragma unroll
        for (int j = 0; j < Rc; j++) st += stop[j];
        g_iscale[bh] = 1.0f / sqrtf((float)Dc * st / sumAll);
    }
}

// ---------------- kernel V: V partial column sums ----------------------------
// grid = BH*NCH (2048) blocks, 256 threads. Independent of everything.
__global__ void __launch_bounds__(256) kV(const float* __restrict__ V) {
    int id  = blockIdx.x;
    int bh  = id >> 3;
    int ch  = id & 7;
    int tid = threadIdx.x;
    const size_t base = (size_t)bh * Sc * Dc;
    const int s0 = ch * CHS;

    int lane4 = tid & 31;
    int rgrp  = tid >> 5;
    const float4* V4 = (const float4*)(V + base);
    float4 acc4 = make_float4(0.f, 0.f, 0.f, 0.f);
    #pragma unroll 8
    for (int s = s0 + rgrp; s < s0 + CHS; s += 8) {
        float4 v = __ldg(&V4[(size_t)s * 32 + lane4]);
        acc4.x += v.x; acc4.y += v.y; acc4.z += v.z; acc4.w += v.w;
    }
    __shared__ float4 sv[8][32];
    sv[rgrp][lane4] = acc4;
    __syncthreads();
    if (rgrp == 0) {
        float4 t = sv[0][lane4];
        #pragma unroll
        for (int g = 1; g < 8; g++) {
            float4 u = sv[g][lane4];
            t.x += u.x; t.y += u.y; t.z += u.z; t.w += u.w;
        }
        ((float4*)&g_vsum[(bh * NCH + ch) * Dc])[lane4] = t;
    }
}

// ---------------- kernel G: approx logits gather -----------------------------
// grid = BH*NCH (2048) blocks, 256 threads; depends on kA.
__global__ void __launch_bounds__(256) kG(const float* __restrict__ K) {
    int id  = blockIdx.x;
    int bh  = id >> 3;
    int ch  = id & 7;
    int tid = threadIdx.x;
    const size_t base = (size_t)bh * Sc * Dc;
    const int s0 = ch * CHS;

    __shared__ int   si1[Rc];
    __shared__ float sq[Rc];
    __shared__ float s_is;
    __shared__ float slog[CHS];     // 2 KB: logits of this chunk
    __shared__ float sred[8];
    __shared__ float s_chm;
    if (tid < Rc) { si1[tid] = g_i1[bh * Rc + tid]; sq[tid] = g_qh[bh * Rc + tid]; }
    if (tid == 0) s_is = g_iscale[bh];
    __syncthreads();
    const float inv_scale = s_is;

    // one half-warp per row (lanes j=0..15 load column si1[j]); software pipeline
    {
        int warp = tid >> 5, lane = tid & 31;
        int half = lane >> 4;
        int j    = lane & 15;
        const float qj  = sq[j];
        const float* Kc = K + base + si1[j];

        float v[8]; int ss[8];
        #pragma unroll
        for (int u = 0; u < 8; u++) {
            ss[u] = s0 + (u * 8 + warp) * 2 + half;
            v[u]  = __ldg(Kc + (size_t)ss[u] * Dc);
        }
        #pragma unroll
        for (int ot = 0; ot < 4; ot++) {
            float vn[8]; int ssn[8];
            if (ot < 3) {
                #pragma unroll
                for (int u = 0; u < 8; u++) {
                    int it = (ot + 1) * 8 + u;
                    ssn[u] = s0 + (it * 8 + warp) * 2 + half;
                    vn[u]  = __ldg(Kc + (size_t)ssn[u] * Dc);
                }
            }
            #pragma unroll
            for (int u = 0; u < 8; u++) {
                float p = qj * v[u];
                #pragma unroll
                for (int o = 8; o; o >>= 1) p += __shfl_down_sync(~0u, p, o, 16);
                if (j == 0) {
                    float lg = p * inv_scale;
                    g_keys[bh * Sc + ss[u]] = f2o(lg);
                    slog[ss[u] - s0] = lg;
                }
            }
            #pragma unroll
            for (int u = 0; u < 8; u++) { v[u] = vn[u]; ss[u] = ssn[u]; }
        }
    }
    __syncthreads();

    // ---- chunk (m, l) partial over the 512 logits ----
    {
        int lane = tid & 31, wid = tid >> 5;
        float m = fmaxf(slog[tid], slog[tid + 256]);
        #pragma unroll
        for (int o = 16; o; o >>= 1) m = fmaxf(m, __shfl_xor_sync(~0u, m, o));
        if (lane == 0) sred[wid] = m;
        __syncthreads();
        if (tid == 0) {
            float mm = sred[0];
            #pragma unroll
            for (int i = 1; i < 8; i++) mm = fmaxf(mm, sred[i]);
            s_chm = mm;
        }
        __syncthreads();
        float M = s_chm;
        float l = __expf(slog[tid] - M) + __expf(slog[tid + 256] - M);
        #pragma unroll
        for (int o = 16; o; o >>= 1) l += __shfl_xor_sync(~0u, l, o);
        if (lane == 0) sred[wid] = l;
        __syncthreads();
        if (tid == 0) {
            float L = 0.f;
            #pragma unroll
            for (int i = 0; i < 8; i++) L += sred[i];
            g_cm[bh * NCH + ch] = M;
            g_cl[bh * NCH + ch] = L;
        }
    }
}

// ---------------- kernel C: top-256 selection + alpha (register radix) ------
// grid = BH (256) blocks, 512 threads. Thread t owns keys [8t, 8t+8).
__global__ void __launch_bounds__(512) kC() {
    int bh   = blockIdx.x;
    int tid  = threadIdx.x;
    int lane = tid & 31, wid = tid >> 5;   // 16 warps

    __shared__ unsigned int hist[256];
    __shared__ int   sel[Ks];
    __shared__ float skey[Ks];             // ordered keys of selected rows (as float bits)
    __shared__ float sred[16];
    __shared__ float s_gmax, s_sumexp;
    __shared__ unsigned int s_prefix;
    __shared__ int s_remaining, cnt, wtot[16];

    // ---- load 8 contiguous keys per thread (2x uint4) ----
    unsigned int k0[8];
    {
        const uint4* K4 = (const uint4*)(g_keys + bh * Sc);
        uint4 a = __ldg(&K4[2 * tid]);
        uint4 b = __ldg(&K4[2 * tid + 1]);
        k0[0] = a.x; k0[1] = a.y; k0[2] = a.z; k0[3] = a.w;
        k0[4] = b.x; k0[5] = b.y; k0[6] = b.z; k0[7] = b.w;
    }
    if (tid == 0) {
        float M = g_cm[bh * NCH];
        #pragma unroll
        for (int c = 1; c < NCH; c++) M = fmaxf(M, g_cm[bh * NCH + c]);
        float L = 0.f;
        #pragma unroll
        for (int c = 0; c < NCH; c++) L += g_cl[bh * NCH + c] * __expf(g_cm[bh * NCH + c] - M);
        s_gmax = M;
        s_sumexp = L;
        s_prefix = 0u; s_remaining = Ks; cnt = 0;
    }
    __syncthreads();
    const float gmax = s_gmax;

    // ---- 4-pass radix select for the 256th-largest key (keys in registers) ----
    for (int shift = 24; shift >= 0; shift -= 8) {
        if (tid < 256) hist[tid] = 0u;
        __syncthreads();
        unsigned int pre   = s_prefix;
        unsigned int pmask = (shift == 24) ? 0u : (0xFFFFFFFFu << (shift + 8));
        #pragma unroll
        for (int i = 0; i < 8; i++) {
            if ((k0[i] & pmask) == pre) atomicAdd(&hist[(k0[i] >> shift) & 0xFFu], 1u);
        }
        __syncthreads();
        // warp-parallel digit scan (warp 0): lane l owns digits [8l, 8l+8)
        if (wid == 0) {
            int h[8]; int psum = 0;
            #pragma unroll
            for (int i = 0; i < 8; i++) { h[i] = (int)hist[8 * lane + i]; psum += h[i]; }
            int rem = s_remaining;
            __syncwarp();
            int S = psum;
            #pragma unroll
            for (int o = 1; o < 32; o <<= 1) {
                int t = __shfl_down_sync(~0u, S, o);
                if (lane + o < 32) S += t;
            }
            int cum = S - psum;   // keys in digits >= 8*(lane+1)
            #pragma unroll
            for (int i = 7; i >= 0; i--) {
                int hi = h[i];
                if (rem > cum && rem <= cum + hi) {
                    s_remaining = rem - cum;
                    s_prefix = pre | ((unsigned int)(8 * lane + i) << shift);
                }
                cum += hi;
            }
        }
        __syncthreads();
    }
    const unsigned int T = s_prefix;
    const int need_ties  = s_remaining;
    const int n_greater  = Ks - need_ties;

    // ---- strictly greater (unordered set), write (sel, key) pairs ----
    #pragma unroll
    for (int i = 0; i < 8; i++) {
        if (k0[i] > T) {
            int p = atomicAdd(&cnt, 1);
            sel[p]  = tid * 8 + i;
            skey[p] = __uint_as_float(k0[i]);
        }
    }
    __syncthreads();

    // ---- ties: single contiguous prefix-scan pass (ascending index) ----
    {
        int cntT = 0;
        #pragma unroll
        for (int i = 0; i < 8; i++) cntT += (k0[i] == T) ? 1 : 0;
        int inc = cntT;
        #pragma unroll
        for (int o = 1; o < 32; o <<= 1) {
            int t = __shfl_up_sync(~0u, inc, o);
            if (lane >= o) inc += t;
        }
        if (lane == 31) wtot[wid] = inc;
        __syncthreads();
        if (tid == 0) {
            int run = 0;
            #pragma unroll
            for (int i = 0; i < 16; i++) { int c = wtot[i]; wtot[i] = run; run += c; }
        }
        __syncthreads();
        int rnk = wtot[wid] + inc - cntT;   // exclusive global rank among ties
        #pragma unroll
        for (int i = 0; i < 8; i++) {
            if (k0[i] == T) {
                if (rnk < need_ties) {
                    sel[n_greater + rnk]  = tid * 8 + i;
                    skey[n_greater + rnk] = __uint_as_float(T);
                }
                rnk++;
            }
        }
    }
    __syncthreads();

    // ---- alpha = sum_sel exp(l-gmax) / sumexp ; write sel ----
    float e = (tid < Ks) ? __expf(o2f(__float_as_uint(skey[tid])) - gmax) : 0.f;
    #pragma unroll
    for (int o = 16; o; o >>= 1) e += __shfl_xor_sync(~0u, e, o);
    if (lane == 0) sred[wid] = e;
    __syncthreads();
    if (tid == 0) {
        float num = 0.f;
        #pragma unroll
        for (int i = 0; i < 16; i++) num += sred[i];
        g_alpha[bh] = num / s_sumexp;
    }
    if (tid < Ks) g_sel[bh * Ks + tid] = sel[tid];
}

// ---------------- kernel E: flash attention partials + fused combine --------
// grid = NSP*BH (1024) blocks, 128 threads (4 warps x 16 rows, lookahead 4).
// Last-finishing split per bh performs the combine (split-K fixup).
__global__ void __launch_bounds__(128) kE(const float* __restrict__ Q,
                                          const float* __restrict__ K,
                                          const float* __restrict__ V,
                                          float* __restrict__ out) {
    int blk = blockIdx.x;
    int bh  = blk >> 2;
    int p   = blk & (NSP - 1);
    int tid = threadIdx.x;
    int lane = tid & 31, wid = tid >> 5;

    __shared__ float sq[Dc];
    __shared__ int   ssel[Ks / NSP];      // 64
    __shared__ float sm[4], sl[4];
    __shared__ float4 sacc[4][32];

    sq[tid] = Q[bh * Dc + tid];
    if (tid < Ks / NSP) ssel[tid] = g_sel[bh * Ks + p * (Ks / NSP) + tid];
    __syncthreads();

    const size_t base = (size_t)bh * Sc * Dc;
    const float inv_sqrtD = 0.08838834764831845f;
    float4 q4 = ((const float4*)sq)[lane];

    // warp handles rows ssel[wid*16 .. wid*16+16), lookahead 4
    float m_run = -INFINITY, l_run = 0.f;
    float4 acc = make_float4(0.f, 0.f, 0.f, 0.f);

    float4 kbuf[4], vbuf[4];
    #pragma unroll
    for (int i = 0; i < 4; i++) {
        int r = ssel[wid * RPW + i];
        kbuf[i] = __ldg(&((const float4*)(K + base + (size_t)r * Dc))[lane]);
        vbuf[i] = __ldg(&((const float4*)(V + base + (size_t)r * Dc))[lane]);
    }
    #pragma unroll
    for (int i = 0; i < RPW; i++) {
        float4 kc = kbuf[i & 3], vc = vbuf[i & 3];
        if (i + 4 < RPW) {
            int r = ssel[wid * RPW + i + 4];
            kbuf[i & 3] = __ldg(&((const float4*)(K + base + (size_t)r * Dc))[lane]);
            vbuf[i & 3] = __ldg(&((const float4*)(V + base + (size_t)r * Dc))[lane]);
        }
        float qk = q4.x * kc.x + q4.y * kc.y + q4.z * kc.z + q4.w * kc.w;
        #pragma unroll
        for (int o = 16; o; o >>= 1) qk += __shfl_xor_sync(~0u, qk, o);
        qk *= inv_sqrtD;

        float mn = fmaxf(m_run, qk);
        float sc = __expf(m_run - mn);
        float ev = __expf(qk - mn);
        l_run = l_run * sc + ev;
        acc.x = acc.x * sc + ev * vc.x;
        acc.y = acc.y * sc + ev * vc.y;
        acc.z = acc.z * sc + ev * vc.z;
        acc.w = acc.w * sc + ev * vc.w;
        m_run = mn;
    }
    if (lane == 0) { sm[wid] = m_run; sl[wid] = l_run; }
    sacc[wid][lane] = acc;
    __syncthreads();

    // warp 0: merge 4 warp partials -> block partial, then maybe combine
    if (wid == 0) {
        float M = fmaxf(fmaxf(sm[0], sm[1]), fmaxf(sm[2], sm[3]));
        float L = 0.f;
        float4 t = make_float4(0.f, 0.f, 0.f, 0.f);
        #pragma unroll
        for (int g = 0; g < 4; g++) {
            float f = __expf(sm[g] - M);
            L += sl[g] * f;
            float4 u = sacc[g][lane];
            t.x += f * u.x; t.y += f * u.y; t.z += f * u.z; t.w += f * u.w;
        }
        if (lane == 0) { g_pm[blk] = M; g_pl[blk] = L; }
        ((float4*)&g_pacc[blk * Dc])[lane] = t;
        __threadfence();

        int old = 0;
        if (lane == 0) old = atomicAdd(&g_cnt[bh], 1);
        old = __shfl_sync(~0u, old, 0);

        if (old == NSP - 1) {
            __threadfence();
            // combine NSP split partials
            float ms[NSP];
            #pragma unroll
            for (int s = 0; s < NSP; s++) ms[s] = __ldcg(&g_pm[bh * NSP + s]);
            float MM = ms[0];
            #pragma unroll
            for (int s = 1; s < NSP; s++) MM = fmaxf(MM, ms[s]);
            float LL = 0.f;
            float4 tt = make_float4(0.f, 0.f, 0.f, 0.f);
            #pragma unroll
            for (int s = 0; s < NSP; s++) {
                float f = __expf(ms[s] - MM);
                LL += __ldcg(&g_pl[bh * NSP + s]) * f;
                float4 u = __ldcg(&((const float4*)&g_pacc[(bh * NSP + s) * Dc])[lane]);
                tt.x += f * u.x; tt.y += f * u.y; tt.z += f * u.z; tt.w += f * u.w;
            }
            float inv_L = 1.0f / LL;

            float4 vm = ((const float4*)&g_vsum[bh * NCH * Dc])[lane];
            #pragma unroll
            for (int c = 1; c < NCH; c++) {
                float4 u = ((const float4*)&g_vsum[(bh * NCH + c) * Dc])[lane];
                vm.x += u.x; vm.y += u.y; vm.z += u.z; vm.w += u.w;
            }
            const float invS = 1.0f / (float)Sc;
            float alpha = g_alpha[bh];
            float4 o;
            o.x = vm.x * invS + alpha * (tt.x * inv_L - vm.x * invS);
            o.y = vm.y * invS + alpha * (tt.y * inv_L - vm.y * invS);
            o.z = vm.z * invS + alpha * (tt.z * inv_L - vm.z * invS);
            o.w = vm.w * invS + alpha * (tt.w * inv_L - vm.w * invS);
            ((float4*)(out + bh * Dc))[lane] = o;

            if (lane == 0) g_cnt[bh] = 0;   // reset for next graph replay
        }
    }
}

// ---------------- launch: fork-join over two streams -------------------------
namespace {
struct StreamCtx {
    cudaStream_t s2;
    cudaEvent_t  evFork, evJoin;
    StreamCtx() {
        cudaStreamCreateWithFlags(&s2, cudaStreamNonBlocking);
        cudaEventCreateWithFlags(&evFork, cudaEventDisableTiming);
        cudaEventCreateWithFlags(&evJoin, cudaEventDisableTiming);
    }
};
}

extern "C" void kernel_launch(void* const* d_in, const int* in_sizes, int n_in,
                              void* d_out, int out_size) {
    static StreamCtx ctx;   // created once, on the first (uncaptured) call

    const float* Q = (const float*)d_in[0];
    const float* K = (const float*)d_in[1];
    const float* V = (const float*)d_in[2];
    float* out = (float*)d_out;

    // fork: V-sweep runs on ctx.s2, concurrent with the kA->kG->kC chain
    cudaEventRecord(ctx.evFork, 0);
    cudaStreamWaitEvent(ctx.s2, ctx.evFork, 0);
    kV<<<BH * NCH, 256, 0, ctx.s2>>>(V);

    kA<<<BH, 128>>>(Q);
    kG<<<BH * NCH, 256>>>(K);
    kC<<<BH, 512>>>();

    // join: kE needs g_vsum (kV) and g_sel/g_alpha (kC)
    cudaEventRecord(ctx.evJoin, ctx.s2);
    cudaStreamWaitEvent(0, ctx.evJoin, 0);
    kE<<<NSP * BH, 128>>>(Q, K, V, out);
}